// round 13
// baseline (speedup 1.0000x reference)
#include <cuda_runtime.h>
#include <cuda_fp16.h>
#include <cstdint>

#define M_ROWS 32768
#define ZC     512
#define DDIM   256
#define KCODES 8192
#define RCAP   8192
#define DELTA  1e-2f
#define ROWB   528          // smem row stride bytes (264 fp16)
#define STG    33792        // 64 rows * ROWB

// ---------------- scratch ----------------
__device__ float g_xT[(size_t)ZC * M_ROWS];
__device__ float g_h[(size_t)M_ROWS * DDIM];
__device__ float g_cbT[(size_t)DDIM * KCODES];
__device__ __half g_hf16[(size_t)M_ROWS * DDIM];
__device__ __half g_cbf16[(size_t)KCODES * DDIM];
__device__ float g_hTr[(size_t)DDIM * RCAP];
__device__ float g_znr[RCAP];
__device__ float g_pv[(size_t)RCAP * 64];
__device__ int   g_pi[(size_t)RCAP * 64];
__device__ float g_enorm[KCODES];
__device__ int   g_idx[M_ROWS];
__device__ int   g_rows[RCAP];
__device__ int   g_nflag;
__device__ float g_part[256];

// ---------------- helpers ----------------
__device__ __forceinline__ void cp16(void* sdst, const void* gsrc){
  unsigned s = (unsigned)__cvta_generic_to_shared(sdst);
  asm volatile("cp.async.cg.shared.global [%0], [%1], 16;\n" :: "r"(s), "l"(gsrc));
}
__device__ __forceinline__ void cp_commit(){ asm volatile("cp.async.commit_group;\n" ::: "memory"); }
__device__ __forceinline__ void cp_wait0(){ asm volatile("cp.async.wait_group 0;\n" ::: "memory"); }
__device__ __forceinline__ void cp_wait1(){ asm volatile("cp.async.wait_group 1;\n" ::: "memory"); }
__device__ __forceinline__ uint32_t smem_u32(const void* p){
  uint32_t a; asm("{ .reg .u64 t; cvta.to.shared.u64 t, %1; cvt.u32.u64 %0, t; }" : "=r"(a) : "l"(p));
  return a;
}
#define LDSM4(r, addr) asm volatile( \
  "ldmatrix.sync.aligned.m8n8.x4.shared.b16 {%0,%1,%2,%3}, [%4];" \
  : "=r"((r)[0]), "=r"((r)[1]), "=r"((r)[2]), "=r"((r)[3]) : "r"(addr))
#define LDSM2(r, addr) asm volatile( \
  "ldmatrix.sync.aligned.m8n8.x2.shared.b16 {%0,%1}, [%2];" \
  : "=r"((r)[0]), "=r"((r)[1]) : "r"(addr))
#define MMA16816(c, a, b) asm volatile( \
  "mma.sync.aligned.m16n8k16.row.col.f32.f16.f16.f32 " \
  "{%0,%1,%2,%3}, {%4,%5,%6,%7}, {%8,%9}, {%0,%1,%2,%3};" \
  : "+f"((c)[0]), "+f"((c)[1]), "+f"((c)[2]), "+f"((c)[3]) \
  : "r"((a)[0]), "r"((a)[1]), "r"((a)[2]), "r"((a)[3]), "r"((b)[0]), "r"((b)[1]))

union SmemGemm {
  struct { float As[2][16][128]; float Bs[2][16][128]; } g;
  struct { float rv[128][16]; int ri[128][16]; } r;
};

// ---------------- transpose (x only) ----------------
__global__ void transpose_k(const float* __restrict__ src, float* __restrict__ dst, int R, int C){
  __shared__ float t[32][33];
  int bx = blockIdx.x * 32, by = blockIdx.y * 32;
  int x = bx + threadIdx.x;
  #pragma unroll
  for (int i = threadIdx.y; i < 32; i += 8) t[i][threadIdx.x] = src[(size_t)(by + i) * C + x];
  __syncthreads();
  int xo = by + threadIdx.x;
  #pragma unroll
  for (int i = threadIdx.y; i < 32; i += 8) dst[(size_t)(bx + i) * R + xo] = t[threadIdx.x][i];
}

// ----- fused codebook prep: cbT + fp16 + exact enorm + nflag reset ---------
__global__ void cb_prep_k(const float* __restrict__ cb){
  __shared__ float buf[32][257];
  const int tid = threadIdx.x;
  int rbase = blockIdx.x * 32;
  for (int lin = tid; lin < 32 * 256; lin += blockDim.x){
    int r = lin >> 8, c = lin & 255;
    float v = cb[(size_t)(rbase + r) * DDIM + c];
    buf[r][c] = v;
    g_cbf16[(size_t)(rbase + r) * DDIM + c] = __float2half_rn(v);
  }
  __syncthreads();
  if (tid < 32){
    int r = tid;
    float s = 0.f;
    #pragma unroll 8
    for (int i = 0; i < 256; i++){ float v = buf[r][i]; s = __fadd_rn(s, __fmul_rn(v, v)); }
    g_enorm[rbase + r] = s;
  }
  for (int lin = tid; lin < 32 * 256; lin += blockDim.x){
    int d = lin >> 5, k = lin & 31;
    g_cbT[(size_t)d * KCODES + rbase + k] = buf[k][d];
  }
  if (blockIdx.x == 0 && tid == 0) g_nflag = 0;
}

// ---------------- GEMM1 exact + fp16 emit ----------------
#define G1_LOAD(kc, buf) do {                                                   \
  int k0_ = (kc) * 16;                                                          \
  cp16(&sm.g.As[buf][lk  ][lr], g_xT + (size_t)(k0_+lk  )*M_ROWS + rbase + lr); \
  cp16(&sm.g.As[buf][lk+8][lr], g_xT + (size_t)(k0_+lk+8)*M_ROWS + rbase + lr); \
  cp16(&sm.g.Bs[buf][lk  ][lr], W    + (size_t)(k0_+lk  )*DDIM   + cbase + lr); \
  cp16(&sm.g.Bs[buf][lk+8][lr], W    + (size_t)(k0_+lk+8)*DDIM   + cbase + lr); \
} while(0)

__global__ __launch_bounds__(256, 2) void gemm1_k(const float* __restrict__ W,
                                                  const float* __restrict__ bias){
  __shared__ SmemGemm sm;
  const int tid = threadIdx.x;
  const int tx = tid & 15, ty = tid >> 4;
  const int rbase = blockIdx.y * 128;
  const int cbase = blockIdx.x * 128;
  const int lk = tid >> 5;
  const int lr = (tid & 31) << 2;

  float acc[8][8];
  #pragma unroll
  for (int i = 0; i < 8; i++)
    #pragma unroll
    for (int j = 0; j < 8; j++) acc[i][j] = 0.f;

  G1_LOAD(0, 0); cp_commit(); cp_wait0(); __syncthreads();
  for (int kc = 0; kc < ZC/16; kc++){
    int cur = kc & 1;
    if (kc + 1 < ZC/16){ G1_LOAD(kc + 1, cur ^ 1); cp_commit(); }
    const float (*Asc)[128] = sm.g.As[cur];
    const float (*Bsc)[128] = sm.g.Bs[cur];
    #pragma unroll
    for (int k = 0; k < 16; k++){
      float4 a0 = *(const float4*)&Asc[k][ty*4];
      float4 a1 = *(const float4*)&Asc[k][64 + ty*4];
      float4 b0 = *(const float4*)&Bsc[k][tx*4];
      float4 b1 = *(const float4*)&Bsc[k][64 + tx*4];
      float a[8] = {a0.x,a0.y,a0.z,a0.w,a1.x,a1.y,a1.z,a1.w};
      float bb[8] = {b0.x,b0.y,b0.z,b0.w,b1.x,b1.y,b1.z,b1.w};
      #pragma unroll
      for (int i = 0; i < 8; i++)
        #pragma unroll
        for (int j = 0; j < 8; j++)
          acc[i][j] = fmaf(a[i], bb[j], acc[i][j]);
    }
    cp_wait0(); __syncthreads();
  }
  #pragma unroll
  for (int jg = 0; jg < 2; jg++){
    int c = cbase + (jg ? 64 + tx*4 : tx*4);
    float4 bv = *(const float4*)&bias[c];
    #pragma unroll
    for (int i = 0; i < 8; i++){
      int r = rbase + ((i < 4) ? ty*4 + i : 64 + ty*4 + (i - 4));
      float4 o;
      o.x = __fadd_rn(acc[i][jg*4+0], bv.x);
      o.y = __fadd_rn(acc[i][jg*4+1], bv.y);
      o.z = __fadd_rn(acc[i][jg*4+2], bv.z);
      o.w = __fadd_rn(acc[i][jg*4+3], bv.w);
      *(float4*)&g_h[(size_t)r * DDIM + c] = o;
      __half2 p01 = __floats2half2_rn(o.x, o.y);
      __half2 p23 = __floats2half2_rn(o.z, o.w);
      uint2 u; u.x = *(uint32_t*)&p01; u.y = *(uint32_t*)&p23;
      *(uint2*)(g_hf16 + (size_t)r * DDIM + c) = u;
    }
  }
}

// -------- approx distance via mma.sync fp16 (256 thr, 2 CTAs/SM) -----------
// CTA = 64 rows; B chunks of 64 codes, 128 chunks; 8 warps 2x4, tile 32x16.
// score = enorm - 2m (zn folded out: per-row shift, argmin/gap invariant)
__global__ __launch_bounds__(256, 2) void approx_mma_k(){
  extern __shared__ char dsm[];
  const uint32_t aB = smem_u32(dsm);
  const int tid = threadIdx.x;
  const int lane = tid & 31, w = tid >> 5;
  const int wm = w >> 2, wn = w & 3;
  const int rbase = blockIdx.x * 64;
  const int gid = lane >> 2, tig = lane & 3;
  const uint32_t bbase[2] = { aB + STG, aB + 2u * STG };

  // A (64 rows) + B chunk 0 in group0; B chunk 1 in group1
  #pragma unroll
  for (int i = 0; i < 8; i++){
    int lin = i * 256 + tid, row = lin >> 5, seg = lin & 31;
    cp16(dsm + row * ROWB + seg * 16, g_hf16 + (size_t)(rbase + row) * 256 + seg * 8);
  }
  #pragma unroll
  for (int i = 0; i < 8; i++){
    int lin = i * 256 + tid, row = lin >> 5, seg = lin & 31;
    cp16(dsm + STG + row * ROWB + seg * 16, g_cbf16 + (size_t)row * 256 + seg * 8);
  }
  cp_commit();
  #pragma unroll
  for (int i = 0; i < 8; i++){
    int lin = i * 256 + tid, row = lin >> 5, seg = lin & 31;
    cp16(dsm + 2 * STG + row * ROWB + seg * 16, g_cbf16 + (size_t)(64 + row) * 256 + seg * 8);
  }
  cp_commit();

  float min1[4], min2[4]; int idx1[4];
  #pragma unroll
  for (int s = 0; s < 4; s++){ min1[s] = 3.4e38f; min2[s] = 3.4e38f; idx1[s] = 0; }

  uint32_t aoff[2], boff[2];
  #pragma unroll
  for (int mi = 0; mi < 2; mi++)
    aoff[mi] = aB + (uint32_t)(wm*32 + mi*16 + (lane & 15)) * ROWB + ((lane >> 4) * 16);
  #pragma unroll
  for (int ni = 0; ni < 2; ni++){
    int l16 = lane & 15;
    boff[ni] = (uint32_t)(wn*16 + ni*8 + (l16 & 7)) * ROWB + ((l16 >> 3) * 16);
  }

  float acc[2][2][4];
  #pragma unroll
  for (int mi = 0; mi < 2; mi++)
    #pragma unroll
    for (int ni = 0; ni < 2; ni++)
      #pragma unroll
      for (int q = 0; q < 4; q++) acc[mi][ni][q] = 0.f;

  for (int ct = 0; ct < 128; ct++){
    if (ct + 1 < 128) cp_wait1(); else cp_wait0();
    __syncthreads();
    uint32_t bb = bbase[ct & 1];
    #pragma unroll 4
    for (int kk = 0; kk < 16; kk++){
      uint32_t ar[2][4], br[2][2];
      #pragma unroll
      for (int mi = 0; mi < 2; mi++) LDSM4(ar[mi], aoff[mi] + kk * 32);
      #pragma unroll
      for (int ni = 0; ni < 2; ni++) LDSM2(br[ni], bb + boff[ni] + kk * 32);
      #pragma unroll
      for (int mi = 0; mi < 2; mi++)
        #pragma unroll
        for (int ni = 0; ni < 2; ni++)
          MMA16816(acc[mi][ni], ar[mi], br[ni]);
    }
    __syncthreads();
    if (ct + 2 < 128){
      int c2 = ct + 2;
      char* dst = dsm + (size_t)STG * (1 + (ct & 1));
      #pragma unroll
      for (int i = 0; i < 8; i++){
        int lin = i * 256 + tid, row = lin >> 5, seg = lin & 31;
        cp16(dst + row * ROWB + seg * 16, g_cbf16 + (size_t)(c2 * 64 + row) * 256 + seg * 8);
      }
      cp_commit();
    }
    // epilogue: scores (en - 2m)
    int cb0 = ct * 64 + wn * 16;
    #pragma unroll
    for (int mi = 0; mi < 2; mi++)
      #pragma unroll
      for (int h = 0; h < 2; h++){
        int s = mi * 2 + h;
        #pragma unroll
        for (int ni = 0; ni < 2; ni++){
          int c = cb0 + ni * 8 + 2 * tig;
          float2 en = __ldg((const float2*)&g_enorm[c]);
          float sc0 = fmaf(-2.f, acc[mi][ni][h*2+0], en.x);
          float sc1 = fmaf(-2.f, acc[mi][ni][h*2+1], en.y);
          if (sc0 < min1[s]){ min2[s] = min1[s]; min1[s] = sc0; idx1[s] = c; }
          else if (sc0 < min2[s]) min2[s] = sc0;
          if (sc1 < min1[s]){ min2[s] = min1[s]; min1[s] = sc1; idx1[s] = c + 1; }
          else if (sc1 < min2[s]) min2[s] = sc1;
          acc[mi][ni][h*2+0] = 0.f;
          acc[mi][ni][h*2+1] = 0.f;
        }
      }
  }

  // cross-thread top-2 merge (16 trackers per row), overlay on A region
  __syncthreads();
  float* rv  = (float*)dsm;            // [64][16]
  float* rv2 = (float*)(dsm + 4096);   // [64][16]
  int*   ri  = (int*)  (dsm + 8192);   // [64][16]
  int cg = wn * 4 + tig;
  #pragma unroll
  for (int s = 0; s < 4; s++){
    int row = wm * 32 + (s >> 1) * 16 + (s & 1) * 8 + gid;
    rv [row * 16 + cg] = min1[s];
    rv2[row * 16 + cg] = min2[s];
    ri [row * 16 + cg] = idx1[s];
  }
  __syncthreads();
  if (tid < 64){
    float bv = rv[tid * 16], bv2 = rv2[tid * 16]; int bi = ri[tid * 16];
    #pragma unroll
    for (int g = 1; g < 16; g++){
      float v = rv[tid * 16 + g], v2 = rv2[tid * 16 + g];
      int ix = ri[tid * 16 + g];
      if (v < bv){ bv2 = fminf(bv, v2); bv = v; bi = ix; }
      else { if (v == bv && ix < bi) bi = ix; bv2 = fminf(bv2, v); }
    }
    g_idx[rbase + tid] = bi;
    if (bv2 - bv < DELTA){
      int sl = atomicAdd(&g_nflag, 1);
      if (sl < RCAP) g_rows[sl] = rbase + tid;
    }
  }
}

// ----- rescue gather: k-major copy + exact znorm (same sequential chain) ---
__global__ void gather_rescue_k(){
  int nf = g_nflag; if (nf > RCAP) nf = RCAP;
  for (int f = blockIdx.x * blockDim.x + threadIdx.x; f < nf; f += gridDim.x * blockDim.x){
    int r = g_rows[f];
    const float* src = g_h + (size_t)r * DDIM;
    float s = 0.f;
    for (int k = 0; k < DDIM; k++){
      float v = src[k];
      s = __fadd_rn(s, __fmul_rn(v, v));
      g_hTr[(size_t)k * RCAP + f] = v;
    }
    g_znr[f] = s;
  }
}

// ------- rescue partial: exact 128x128 tile, code-split over blockIdx.x ----
__global__ __launch_bounds__(256, 2) void rescue_part_k(){
  int nf = g_nflag; if (nf > RCAP) nf = RCAP;
  if ((int)blockIdx.y * 128 >= nf) return;
  __shared__ SmemGemm sm;
  const int tid = threadIdx.x;
  const int tx = tid & 15, ty = tid >> 4;
  const int rbase = blockIdx.y * 128;
  const int cbase = blockIdx.x * 128;
  const int lk = tid >> 5;
  const int lr = (tid & 31) << 2;

  float acc[8][8];
  #pragma unroll
  for (int i = 0; i < 8; i++)
    #pragma unroll
    for (int j = 0; j < 8; j++) acc[i][j] = 0.f;

#define RS_LOAD(kc, buf) do {                                                     \
  int k0_ = (kc) * 16;                                                            \
  cp16(&sm.g.As[buf][lk  ][lr], g_hTr + (size_t)(k0_+lk  )*RCAP   + rbase + lr);  \
  cp16(&sm.g.As[buf][lk+8][lr], g_hTr + (size_t)(k0_+lk+8)*RCAP   + rbase + lr);  \
  cp16(&sm.g.Bs[buf][lk  ][lr], g_cbT + (size_t)(k0_+lk  )*KCODES + cbase + lr);  \
  cp16(&sm.g.Bs[buf][lk+8][lr], g_cbT + (size_t)(k0_+lk+8)*KCODES + cbase + lr);  \
} while(0)

  RS_LOAD(0, 0); cp_commit(); cp_wait0(); __syncthreads();
  for (int kc = 0; kc < DDIM/16; kc++){
    int cur = kc & 1;
    if (kc + 1 < DDIM/16){ RS_LOAD(kc + 1, cur ^ 1); cp_commit(); }
    const float (*Asc)[128] = sm.g.As[cur];
    const float (*Bsc)[128] = sm.g.Bs[cur];
    #pragma unroll
    for (int k = 0; k < 16; k++){
      float4 a0 = *(const float4*)&Asc[k][ty*4];
      float4 a1 = *(const float4*)&Asc[k][64 + ty*4];
      float4 b0 = *(const float4*)&Bsc[k][tx*4];
      float4 b1 = *(const float4*)&Bsc[k][64 + tx*4];
      float a[8] = {a0.x,a0.y,a0.z,a0.w,a1.x,a1.y,a1.z,a1.w};
      float bb[8] = {b0.x,b0.y,b0.z,b0.w,b1.x,b1.y,b1.z,b1.w};
      #pragma unroll
      for (int i = 0; i < 8; i++)
        #pragma unroll
        for (int j = 0; j < 8; j++)
          acc[i][j] = fmaf(a[i], bb[j], acc[i][j]);
    }
    cp_wait0(); __syncthreads();
  }
  float minv[8]; int mini[8]; float zn[8];
  #pragma unroll
  for (int i = 0; i < 8; i++){
    minv[i] = 3.4e38f; mini[i] = 0;
    int rl = (i < 4) ? ty*4 + i : 64 + ty*4 + (i - 4);
    zn[i] = g_znr[rbase + rl];
  }
  #pragma unroll
  for (int j = 0; j < 8; j++){
    int cl = (j < 4) ? tx*4 + j : 64 + tx*4 + (j - 4);
    int c = cbase + cl;
    float e = __ldg(&g_enorm[c]);
    #pragma unroll
    for (int i = 0; i < 8; i++){
      float t  = __fadd_rn(zn[i], e);
      float u2 = __fmul_rn(2.0f, acc[i][j]);
      float sc = __fsub_rn(t, u2);
      if (sc < minv[i]){ minv[i] = sc; mini[i] = c; }
    }
  }
  __syncthreads();
  #pragma unroll
  for (int i = 0; i < 8; i++){
    int rl = (i < 4) ? ty*4 + i : 64 + ty*4 + (i - 4);
    sm.r.rv[rl][tx] = minv[i];
    sm.r.ri[rl][tx] = mini[i];
  }
  __syncthreads();
  if (tid < 128){
    float bv = sm.r.rv[tid][0]; int bi = sm.r.ri[tid][0];
    #pragma unroll
    for (int t = 1; t < 16; t++){
      float v = sm.r.rv[tid][t]; int ix = sm.r.ri[tid][t];
      if (v < bv || (v == bv && ix < bi)){ bv = v; bi = ix; }
    }
    g_pv[(size_t)(rbase + tid) * 64 + blockIdx.x] = bv;
    g_pi[(size_t)(rbase + tid) * 64 + blockIdx.x] = bi;
  }
}

__global__ void rescue_final_k(){
  int nf = g_nflag; if (nf > RCAP) nf = RCAP;
  int f = blockIdx.x * blockDim.x + threadIdx.x;
  if (f >= nf) return;
  float bv = g_pv[(size_t)f * 64]; int bi = g_pi[(size_t)f * 64];
  for (int kt = 1; kt < 64; kt++){
    float v = g_pv[(size_t)f * 64 + kt];
    int ix = g_pi[(size_t)f * 64 + kt];
    if (v < bv || (v == bv && ix < bi)){ bv = v; bi = ix; }
  }
  g_idx[g_rows[f]] = bi;
}

// ---------------- gather/loss ----------------
__global__ void gather_loss_k(const float* __restrict__ cb, float* __restrict__ out){
  const int tid = threadIdx.x;
  const int rbase = blockIdx.x * 128;
  float s = 0.f;
  #pragma unroll 4
  for (int p = 0; p < 32; p++){
    int lin = p * 256 + tid;
    int r = rbase + (lin >> 6);
    int c = (lin & 63) << 2;
    int id = __ldg(&g_idx[r]);
    float4 e  = *(const float4*)&cb[(size_t)id * DDIM + c];
    float4 hh = *(const float4*)&g_h[(size_t)r * DDIM + c];
    float dx = e.x - hh.x, dy = e.y - hh.y, dz = e.z - hh.z, dw = e.w - hh.w;
    s += dx*dx + dy*dy + dz*dz + dw*dw;
    *(float4*)&out[(size_t)r * DDIM + c] = e;
  }
  __shared__ float red[256];
  red[tid] = s; __syncthreads();
  #pragma unroll
  for (int o = 128; o > 0; o >>= 1){
    if (tid < o) red[tid] += red[tid + o];
    __syncthreads();
  }
  if (tid == 0) g_part[blockIdx.x] = red[0];
}

__global__ void final_loss_k(float* __restrict__ out, long long pos){
  __shared__ float red[256];
  int tid = threadIdx.x;
  red[tid] = g_part[tid];
  __syncthreads();
  #pragma unroll
  for (int o = 128; o > 0; o >>= 1){
    if (tid < o) red[tid] += red[tid + o];
    __syncthreads();
  }
  if (tid == 0) out[pos] = 1.25f * red[0] / 8388608.0f;
}

// ---------------- launch ----------------
extern "C" void kernel_launch(void* const* d_in, const int* in_sizes, int n_in,
                              void* d_out, int out_size){
  (void)in_sizes; (void)n_in;
  const float* x  = (const float*)d_in[0];
  const float* W  = (const float*)d_in[1];
  const float* b  = (const float*)d_in[2];
  const float* cb = (const float*)d_in[3];
  float* out = (float*)d_out;

  void *pxT = 0;
  cudaGetSymbolAddress(&pxT, g_xT);

  const int DSM = 3 * STG;   // A + 2 B stages = 99 KB -> 2 CTAs/SM
  cudaFuncSetAttribute(approx_mma_k, cudaFuncAttributeMaxDynamicSharedMemorySize, DSM);

  transpose_k<<<dim3(ZC/32, M_ROWS/32), dim3(32,8)>>>(x, (float*)pxT, M_ROWS, ZC);
  cb_prep_k<<<KCODES/32, 256>>>(cb);
  gemm1_k<<<dim3(DDIM/128, M_ROWS/128), 256>>>(W, b);
  approx_mma_k<<<M_ROWS/64, 256, DSM>>>();        // launch #4 -> profiled
  gather_rescue_k<<<16, 256>>>();
  rescue_part_k<<<dim3(64, RCAP/128), 256>>>();
  rescue_final_k<<<RCAP/128, 128>>>();
  gather_loss_k<<<256, 256>>>(cb, out);
  final_loss_k<<<1, 256>>>(out, (long long)out_size - 1);
}

// round 14
// speedup vs baseline: 1.0389x; 1.0389x over previous
#include <cuda_runtime.h>
#include <cuda_fp16.h>
#include <cstdint>

#define M_ROWS 32768
#define ZC     512
#define DDIM   256
#define KCODES 8192
#define RCAP   8192
#define DELTA  1e-2f
#define ROWB   528          // smem row stride bytes (264 fp16)

// ---------------- scratch ----------------
__device__ float g_xT[(size_t)ZC * M_ROWS];
__device__ float g_h[(size_t)M_ROWS * DDIM];
__device__ float g_cbT[(size_t)DDIM * KCODES];
__device__ __half g_hf16[(size_t)M_ROWS * DDIM];
__device__ __half g_cbf16[(size_t)KCODES * DDIM];
__device__ float g_hTr[(size_t)DDIM * RCAP];
__device__ float g_znr[RCAP];
__device__ float g_pv[(size_t)RCAP * 64];
__device__ int   g_pi[(size_t)RCAP * 64];
__device__ float g_enorm[KCODES];
__device__ int   g_idx[M_ROWS];
__device__ int   g_rows[RCAP];
__device__ int   g_nflag;
__device__ float g_part[256];

// ---------------- helpers ----------------
__device__ __forceinline__ void cp16(void* sdst, const void* gsrc){
  unsigned s = (unsigned)__cvta_generic_to_shared(sdst);
  asm volatile("cp.async.cg.shared.global [%0], [%1], 16;\n" :: "r"(s), "l"(gsrc));
}
__device__ __forceinline__ void cp_commit(){ asm volatile("cp.async.commit_group;\n" ::: "memory"); }
__device__ __forceinline__ void cp_wait0(){ asm volatile("cp.async.wait_group 0;\n" ::: "memory"); }
__device__ __forceinline__ void cp_wait1(){ asm volatile("cp.async.wait_group 1;\n" ::: "memory"); }
__device__ __forceinline__ uint32_t smem_u32(const void* p){
  uint32_t a; asm("{ .reg .u64 t; cvta.to.shared.u64 t, %1; cvt.u32.u64 %0, t; }" : "=r"(a) : "l"(p));
  return a;
}
#define LDSM4(r, addr) asm volatile( \
  "ldmatrix.sync.aligned.m8n8.x4.shared.b16 {%0,%1,%2,%3}, [%4];" \
  : "=r"((r)[0]), "=r"((r)[1]), "=r"((r)[2]), "=r"((r)[3]) : "r"(addr))
#define MMA16816(c, a, b) asm volatile( \
  "mma.sync.aligned.m16n8k16.row.col.f32.f16.f16.f32 " \
  "{%0,%1,%2,%3}, {%4,%5,%6,%7}, {%8,%9}, {%0,%1,%2,%3};" \
  : "+f"((c)[0]), "+f"((c)[1]), "+f"((c)[2]), "+f"((c)[3]) \
  : "r"((a)[0]), "r"((a)[1]), "r"((a)[2]), "r"((a)[3]), "r"((b)[0]), "r"((b)[1]))

union SmemGemm {
  struct { float As[2][16][128]; float Bs[2][16][128]; } g;
  struct { float rv[128][16]; int ri[128][16]; } r;
};

// ---------------- transpose (x only) ----------------
__global__ void transpose_k(const float* __restrict__ src, float* __restrict__ dst, int R, int C){
  __shared__ float t[32][33];
  int bx = blockIdx.x * 32, by = blockIdx.y * 32;
  int x = bx + threadIdx.x;
  #pragma unroll
  for (int i = threadIdx.y; i < 32; i += 8) t[i][threadIdx.x] = src[(size_t)(by + i) * C + x];
  __syncthreads();
  int xo = by + threadIdx.x;
  #pragma unroll
  for (int i = threadIdx.y; i < 32; i += 8) dst[(size_t)(bx + i) * R + xo] = t[threadIdx.x][i];
}

// ----- fused codebook prep: cbT + fp16 + exact enorm + nflag reset ---------
__global__ void cb_prep_k(const float* __restrict__ cb){
  __shared__ float buf[32][257];
  const int tid = threadIdx.x;
  int rbase = blockIdx.x * 32;
  for (int lin = tid; lin < 32 * 256; lin += blockDim.x){
    int r = lin >> 8, c = lin & 255;
    float v = cb[(size_t)(rbase + r) * DDIM + c];
    buf[r][c] = v;
    g_cbf16[(size_t)(rbase + r) * DDIM + c] = __float2half_rn(v);
  }
  __syncthreads();
  if (tid < 32){
    int r = tid;
    float s = 0.f;
    #pragma unroll 8
    for (int i = 0; i < 256; i++){ float v = buf[r][i]; s = __fadd_rn(s, __fmul_rn(v, v)); }
    g_enorm[rbase + r] = s;
  }
  for (int lin = tid; lin < 32 * 256; lin += blockDim.x){
    int d = lin >> 5, k = lin & 31;
    g_cbT[(size_t)d * KCODES + rbase + k] = buf[k][d];
  }
  if (blockIdx.x == 0 && tid == 0) g_nflag = 0;
}

// ---------------- GEMM1 exact + fp16 emit ----------------
#define G1_LOAD(kc, buf) do {                                                   \
  int k0_ = (kc) * 16;                                                          \
  cp16(&sm.g.As[buf][lk  ][lr], g_xT + (size_t)(k0_+lk  )*M_ROWS + rbase + lr); \
  cp16(&sm.g.As[buf][lk+8][lr], g_xT + (size_t)(k0_+lk+8)*M_ROWS + rbase + lr); \
  cp16(&sm.g.Bs[buf][lk  ][lr], W    + (size_t)(k0_+lk  )*DDIM   + cbase + lr); \
  cp16(&sm.g.Bs[buf][lk+8][lr], W    + (size_t)(k0_+lk+8)*DDIM   + cbase + lr); \
} while(0)

__global__ __launch_bounds__(256, 2) void gemm1_k(const float* __restrict__ W,
                                                  const float* __restrict__ bias){
  __shared__ SmemGemm sm;
  const int tid = threadIdx.x;
  const int tx = tid & 15, ty = tid >> 4;
  const int rbase = blockIdx.y * 128;
  const int cbase = blockIdx.x * 128;
  const int lk = tid >> 5;
  const int lr = (tid & 31) << 2;

  float acc[8][8];
  #pragma unroll
  for (int i = 0; i < 8; i++)
    #pragma unroll
    for (int j = 0; j < 8; j++) acc[i][j] = 0.f;

  G1_LOAD(0, 0); cp_commit(); cp_wait0(); __syncthreads();
  for (int kc = 0; kc < ZC/16; kc++){
    int cur = kc & 1;
    if (kc + 1 < ZC/16){ G1_LOAD(kc + 1, cur ^ 1); cp_commit(); }
    const float (*Asc)[128] = sm.g.As[cur];
    const float (*Bsc)[128] = sm.g.Bs[cur];
    #pragma unroll
    for (int k = 0; k < 16; k++){
      float4 a0 = *(const float4*)&Asc[k][ty*4];
      float4 a1 = *(const float4*)&Asc[k][64 + ty*4];
      float4 b0 = *(const float4*)&Bsc[k][tx*4];
      float4 b1 = *(const float4*)&Bsc[k][64 + tx*4];
      float a[8] = {a0.x,a0.y,a0.z,a0.w,a1.x,a1.y,a1.z,a1.w};
      float bb[8] = {b0.x,b0.y,b0.z,b0.w,b1.x,b1.y,b1.z,b1.w};
      #pragma unroll
      for (int i = 0; i < 8; i++)
        #pragma unroll
        for (int j = 0; j < 8; j++)
          acc[i][j] = fmaf(a[i], bb[j], acc[i][j]);
    }
    cp_wait0(); __syncthreads();
  }
  #pragma unroll
  for (int jg = 0; jg < 2; jg++){
    int c = cbase + (jg ? 64 + tx*4 : tx*4);
    float4 bv = *(const float4*)&bias[c];
    #pragma unroll
    for (int i = 0; i < 8; i++){
      int r = rbase + ((i < 4) ? ty*4 + i : 64 + ty*4 + (i - 4));
      float4 o;
      o.x = __fadd_rn(acc[i][jg*4+0], bv.x);
      o.y = __fadd_rn(acc[i][jg*4+1], bv.y);
      o.z = __fadd_rn(acc[i][jg*4+2], bv.z);
      o.w = __fadd_rn(acc[i][jg*4+3], bv.w);
      *(float4*)&g_h[(size_t)r * DDIM + c] = o;
      __half2 p01 = __floats2half2_rn(o.x, o.y);
      __half2 p23 = __floats2half2_rn(o.z, o.w);
      uint2 u; u.x = *(uint32_t*)&p01; u.y = *(uint32_t*)&p23;
      *(uint2*)(g_hf16 + (size_t)r * DDIM + c) = u;
    }
  }
}

// -------- approx distance via mma.sync fp16 (512 thr, frag-pipelined) ------
// R12 geometry: CTA=128 rows, 64 B-chunks of 128 codes, 16 warps 4x4,
// warp tile 32x32. B loaded via ldmatrix.x4; fragments double-buffered so
// MMAs never wait on the just-issued LDSM. score = enorm - 2m.
__global__ __launch_bounds__(512, 1) void approx_mma_k(){
  extern __shared__ char dsm[];
  const uint32_t aB = smem_u32(dsm);
  const int tid = threadIdx.x;
  const int lane = tid & 31, w = tid >> 5;
  const int wm = w >> 2, wn = w & 3;
  const int rbase = blockIdx.x * 128;
  const int gid = lane >> 2, tig = lane & 3;
  const uint32_t bbase[2] = { aB + 67584u, aB + 135168u };

  #pragma unroll
  for (int i = 0; i < 8; i++){
    int lin = i * 512 + tid, row = lin >> 5, seg = lin & 31;
    cp16(dsm + row * ROWB + seg * 16, g_hf16 + (size_t)(rbase + row) * 256 + seg * 8);
  }
  #pragma unroll
  for (int i = 0; i < 8; i++){
    int lin = i * 512 + tid, row = lin >> 5, seg = lin & 31;
    cp16(dsm + 67584 + row * ROWB + seg * 16, g_cbf16 + (size_t)row * 256 + seg * 8);
  }
  cp_commit();
  #pragma unroll
  for (int i = 0; i < 8; i++){
    int lin = i * 512 + tid, row = lin >> 5, seg = lin & 31;
    cp16(dsm + 135168 + row * ROWB + seg * 16, g_cbf16 + (size_t)(128 + row) * 256 + seg * 8);
  }
  cp_commit();

  float min1[4], min2[4]; int idx1[4];
  #pragma unroll
  for (int s = 0; s < 4; s++){ min1[s] = 3.4e38f; min2[s] = 3.4e38f; idx1[s] = 0; }

  // A addr (x4): rows wm*32+mi*16+(lane&15), +((lane>>4)*16) bytes
  uint32_t aoff[2];
  #pragma unroll
  for (int mi = 0; mi < 2; mi++)
    aoff[mi] = aB + (uint32_t)(wm*32 + mi*16 + (lane & 15)) * ROWB + ((lane >> 4) * 16);
  // B addr (x4): 16-col group ni: rows wn*32+ni*16+((g>>1)&1)*8+(lane&7), +(g&1)*16
  uint32_t boff[2];
  {
    int g = lane >> 3;
    #pragma unroll
    for (int ni = 0; ni < 2; ni++)
      boff[ni] = (uint32_t)(wn*32 + ni*16 + ((g >> 1) & 1) * 8 + (lane & 7)) * ROWB
                 + ((g & 1) * 16);
  }

  float acc[2][4][4];
  #pragma unroll
  for (int mi = 0; mi < 2; mi++)
    #pragma unroll
    for (int ni = 0; ni < 4; ni++)
      #pragma unroll
      for (int q = 0; q < 4; q++) acc[mi][ni][q] = 0.f;

  for (int ct = 0; ct < 64; ct++){
    if (ct + 1 < 64) cp_wait1(); else cp_wait0();
    __syncthreads();
    uint32_t bb = bbase[ct & 1];

    uint32_t ar[2][2][4], br[2][2][4];   // [parity][tile][regs]
    // preload kk = 0
    LDSM4(ar[0][0], aoff[0]); LDSM4(ar[0][1], aoff[1]);
    LDSM4(br[0][0], bb + boff[0]); LDSM4(br[0][1], bb + boff[1]);
    #pragma unroll
    for (int kk = 0; kk < 16; kk++){
      int p = kk & 1;
      if (kk < 15){
        LDSM4(ar[p^1][0], aoff[0] + (kk+1) * 32);
        LDSM4(ar[p^1][1], aoff[1] + (kk+1) * 32);
        LDSM4(br[p^1][0], bb + boff[0] + (kk+1) * 32);
        LDSM4(br[p^1][1], bb + boff[1] + (kk+1) * 32);
      }
      #pragma unroll
      for (int mi = 0; mi < 2; mi++)
        #pragma unroll
        for (int j = 0; j < 4; j++)
          MMA16816(acc[mi][j], ar[p][mi], &br[p][j >> 1][(j & 1) * 2]);
    }
    __syncthreads();
    if (ct + 2 < 64){
      int c2 = ct + 2;
      char* dst = dsm + (size_t)67584 * (1 + (ct & 1));
      #pragma unroll
      for (int i = 0; i < 8; i++){
        int lin = i * 512 + tid, row = lin >> 5, seg = lin & 31;
        cp16(dst + row * ROWB + seg * 16, g_cbf16 + (size_t)(c2 * 128 + row) * 256 + seg * 8);
      }
      cp_commit();
    }
    // epilogue: scores (en - 2m)
    int cb0 = ct * 128 + wn * 32;
    #pragma unroll
    for (int mi = 0; mi < 2; mi++)
      #pragma unroll
      for (int h = 0; h < 2; h++){
        int s = mi * 2 + h;
        #pragma unroll
        for (int ni = 0; ni < 4; ni++){
          int c = cb0 + ni * 8 + 2 * tig;
          float2 en = __ldg((const float2*)&g_enorm[c]);
          float sc0 = fmaf(-2.f, acc[mi][ni][h*2+0], en.x);
          float sc1 = fmaf(-2.f, acc[mi][ni][h*2+1], en.y);
          if (sc0 < min1[s]){ min2[s] = min1[s]; min1[s] = sc0; idx1[s] = c; }
          else if (sc0 < min2[s]) min2[s] = sc0;
          if (sc1 < min1[s]){ min2[s] = min1[s]; min1[s] = sc1; idx1[s] = c + 1; }
          else if (sc1 < min2[s]) min2[s] = sc1;
          acc[mi][ni][h*2+0] = 0.f;
          acc[mi][ni][h*2+1] = 0.f;
        }
      }
  }

  // cross-thread top-2 merge (16 col-groups per row), overlay on A region
  __syncthreads();
  float* rv  = (float*)dsm;
  float* rv2 = (float*)(dsm + 8192);
  int*   ri  = (int*)  (dsm + 16384);
  int cg = wn * 4 + tig;
  #pragma unroll
  for (int s = 0; s < 4; s++){
    int row = wm * 32 + (s >> 1) * 16 + (s & 1) * 8 + gid;
    rv [row * 16 + cg] = min1[s];
    rv2[row * 16 + cg] = min2[s];
    ri [row * 16 + cg] = idx1[s];
  }
  __syncthreads();
  if (tid < 128){
    float bv = rv[tid * 16], bv2 = rv2[tid * 16]; int bi = ri[tid * 16];
    #pragma unroll
    for (int g = 1; g < 16; g++){
      float v = rv[tid * 16 + g], v2 = rv2[tid * 16 + g];
      int ix = ri[tid * 16 + g];
      if (v < bv){ bv2 = fminf(bv, v2); bv = v; bi = ix; }
      else { if (v == bv && ix < bi) bi = ix; bv2 = fminf(bv2, v); }
    }
    g_idx[rbase + tid] = bi;
    if (bv2 - bv < DELTA){
      int sl = atomicAdd(&g_nflag, 1);
      if (sl < RCAP) g_rows[sl] = rbase + tid;
    }
  }
}

// ----- rescue gather: k-major copy + exact znorm (same sequential chain) ---
__global__ void gather_rescue_k(){
  int nf = g_nflag; if (nf > RCAP) nf = RCAP;
  for (int f = blockIdx.x * blockDim.x + threadIdx.x; f < nf; f += gridDim.x * blockDim.x){
    int r = g_rows[f];
    const float* src = g_h + (size_t)r * DDIM;
    float s = 0.f;
    for (int k = 0; k < DDIM; k++){
      float v = src[k];
      s = __fadd_rn(s, __fmul_rn(v, v));
      g_hTr[(size_t)k * RCAP + f] = v;
    }
    g_znr[f] = s;
  }
}

// ------- rescue partial: exact 128x128 tile, code-split over blockIdx.x ----
__global__ __launch_bounds__(256, 2) void rescue_part_k(){
  int nf = g_nflag; if (nf > RCAP) nf = RCAP;
  if ((int)blockIdx.y * 128 >= nf) return;
  __shared__ SmemGemm sm;
  const int tid = threadIdx.x;
  const int tx = tid & 15, ty = tid >> 4;
  const int rbase = blockIdx.y * 128;
  const int cbase = blockIdx.x * 128;
  const int lk = tid >> 5;
  const int lr = (tid & 31) << 2;

  float acc[8][8];
  #pragma unroll
  for (int i = 0; i < 8; i++)
    #pragma unroll
    for (int j = 0; j < 8; j++) acc[i][j] = 0.f;

#define RS_LOAD(kc, buf) do {                                                     \
  int k0_ = (kc) * 16;                                                            \
  cp16(&sm.g.As[buf][lk  ][lr], g_hTr + (size_t)(k0_+lk  )*RCAP   + rbase + lr);  \
  cp16(&sm.g.As[buf][lk+8][lr], g_hTr + (size_t)(k0_+lk+8)*RCAP   + rbase + lr);  \
  cp16(&sm.g.Bs[buf][lk  ][lr], g_cbT + (size_t)(k0_+lk  )*KCODES + cbase + lr);  \
  cp16(&sm.g.Bs[buf][lk+8][lr], g_cbT + (size_t)(k0_+lk+8)*KCODES + cbase + lr);  \
} while(0)

  RS_LOAD(0, 0); cp_commit(); cp_wait0(); __syncthreads();
  for (int kc = 0; kc < DDIM/16; kc++){
    int cur = kc & 1;
    if (kc + 1 < DDIM/16){ RS_LOAD(kc + 1, cur ^ 1); cp_commit(); }
    const float (*Asc)[128] = sm.g.As[cur];
    const float (*Bsc)[128] = sm.g.Bs[cur];
    #pragma unroll
    for (int k = 0; k < 16; k++){
      float4 a0 = *(const float4*)&Asc[k][ty*4];
      float4 a1 = *(const float4*)&Asc[k][64 + ty*4];
      float4 b0 = *(const float4*)&Bsc[k][tx*4];
      float4 b1 = *(const float4*)&Bsc[k][64 + tx*4];
      float a[8] = {a0.x,a0.y,a0.z,a0.w,a1.x,a1.y,a1.z,a1.w};
      float bb[8] = {b0.x,b0.y,b0.z,b0.w,b1.x,b1.y,b1.z,b1.w};
      #pragma unroll
      for (int i = 0; i < 8; i++)
        #pragma unroll
        for (int j = 0; j < 8; j++)
          acc[i][j] = fmaf(a[i], bb[j], acc[i][j]);
    }
    cp_wait0(); __syncthreads();
  }
  float minv[8]; int mini[8]; float zn[8];
  #pragma unroll
  for (int i = 0; i < 8; i++){
    minv[i] = 3.4e38f; mini[i] = 0;
    int rl = (i < 4) ? ty*4 + i : 64 + ty*4 + (i - 4);
    zn[i] = g_znr[rbase + rl];
  }
  #pragma unroll
  for (int j = 0; j < 8; j++){
    int cl = (j < 4) ? tx*4 + j : 64 + tx*4 + (j - 4);
    int c = cbase + cl;
    float e = __ldg(&g_enorm[c]);
    #pragma unroll
    for (int i = 0; i < 8; i++){
      float t  = __fadd_rn(zn[i], e);
      float u2 = __fmul_rn(2.0f, acc[i][j]);
      float sc = __fsub_rn(t, u2);
      if (sc < minv[i]){ minv[i] = sc; mini[i] = c; }
    }
  }
  __syncthreads();
  #pragma unroll
  for (int i = 0; i < 8; i++){
    int rl = (i < 4) ? ty*4 + i : 64 + ty*4 + (i - 4);
    sm.r.rv[rl][tx] = minv[i];
    sm.r.ri[rl][tx] = mini[i];
  }
  __syncthreads();
  if (tid < 128){
    float bv = sm.r.rv[tid][0]; int bi = sm.r.ri[tid][0];
    #pragma unroll
    for (int t = 1; t < 16; t++){
      float v = sm.r.rv[tid][t]; int ix = sm.r.ri[tid][t];
      if (v < bv || (v == bv && ix < bi)){ bv = v; bi = ix; }
    }
    g_pv[(size_t)(rbase + tid) * 64 + blockIdx.x] = bv;
    g_pi[(size_t)(rbase + tid) * 64 + blockIdx.x] = bi;
  }
}

__global__ void rescue_final_k(){
  int nf = g_nflag; if (nf > RCAP) nf = RCAP;
  int f = blockIdx.x * blockDim.x + threadIdx.x;
  if (f >= nf) return;
  float bv = g_pv[(size_t)f * 64]; int bi = g_pi[(size_t)f * 64];
  for (int kt = 1; kt < 64; kt++){
    float v = g_pv[(size_t)f * 64 + kt];
    int ix = g_pi[(size_t)f * 64 + kt];
    if (v < bv || (v == bv && ix < bi)){ bv = v; bi = ix; }
  }
  g_idx[g_rows[f]] = bi;
}

// ---------------- gather/loss ----------------
__global__ void gather_loss_k(const float* __restrict__ cb, float* __restrict__ out){
  const int tid = threadIdx.x;
  const int rbase = blockIdx.x * 128;
  float s = 0.f;
  #pragma unroll 4
  for (int p = 0; p < 32; p++){
    int lin = p * 256 + tid;
    int r = rbase + (lin >> 6);
    int c = (lin & 63) << 2;
    int id = __ldg(&g_idx[r]);
    float4 e  = *(const float4*)&cb[(size_t)id * DDIM + c];
    float4 hh = *(const float4*)&g_h[(size_t)r * DDIM + c];
    float dx = e.x - hh.x, dy = e.y - hh.y, dz = e.z - hh.z, dw = e.w - hh.w;
    s += dx*dx + dy*dy + dz*dz + dw*dw;
    *(float4*)&out[(size_t)r * DDIM + c] = e;
  }
  __shared__ float red[256];
  red[tid] = s; __syncthreads();
  #pragma unroll
  for (int o = 128; o > 0; o >>= 1){
    if (tid < o) red[tid] += red[tid + o];
    __syncthreads();
  }
  if (tid == 0) g_part[blockIdx.x] = red[0];
}

__global__ void final_loss_k(float* __restrict__ out, long long pos){
  __shared__ float red[256];
  int tid = threadIdx.x;
  red[tid] = g_part[tid];
  __syncthreads();
  #pragma unroll
  for (int o = 128; o > 0; o >>= 1){
    if (tid < o) red[tid] += red[tid + o];
    __syncthreads();
  }
  if (tid == 0) out[pos] = 1.25f * red[0] / 8388608.0f;
}

// ---------------- launch ----------------
extern "C" void kernel_launch(void* const* d_in, const int* in_sizes, int n_in,
                              void* d_out, int out_size){
  (void)in_sizes; (void)n_in;
  const float* x  = (const float*)d_in[0];
  const float* W  = (const float*)d_in[1];
  const float* b  = (const float*)d_in[2];
  const float* cb = (const float*)d_in[3];
  float* out = (float*)d_out;

  void *pxT = 0;
  cudaGetSymbolAddress(&pxT, g_xT);

  const int DSM = 3 * 67584;   // A + 2 B stages = 198 KB
  cudaFuncSetAttribute(approx_mma_k, cudaFuncAttributeMaxDynamicSharedMemorySize, DSM);

  transpose_k<<<dim3(ZC/32, M_ROWS/32), dim3(32,8)>>>(x, (float*)pxT, M_ROWS, ZC);
  cb_prep_k<<<KCODES/32, 256>>>(cb);
  gemm1_k<<<dim3(DDIM/128, M_ROWS/128), 256>>>(W, b);
  approx_mma_k<<<M_ROWS/128, 512, DSM>>>();       // launch #4 -> profiled
  gather_rescue_k<<<16, 256>>>();
  rescue_part_k<<<dim3(64, RCAP/128), 256>>>();
  rescue_final_k<<<RCAP/128, 128>>>();
  gather_loss_k<<<256, 256>>>(cb, out);
  final_loss_k<<<1, 256>>>(out, (long long)out_size - 1);
}

// round 15
// speedup vs baseline: 1.0488x; 1.0095x over previous
#include <cuda_runtime.h>
#include <cuda_fp16.h>
#include <cstdint>

#define M_ROWS 32768
#define ZC     512
#define DDIM   256
#define KCODES 8192
#define RCAP   8192
#define DELTA  1e-2f
#define ROWB   528          // smem row stride bytes (264 fp16)

// ---------------- scratch ----------------
__device__ float g_xT[(size_t)ZC * M_ROWS];
__device__ float g_h[(size_t)M_ROWS * DDIM];
__device__ float g_cbT[(size_t)DDIM * KCODES];
__device__ __half g_hf16[(size_t)M_ROWS * DDIM];
__device__ __half g_cbf16[(size_t)KCODES * DDIM];
__device__ float g_hTr[(size_t)DDIM * RCAP];
__device__ float g_znr[RCAP];
__device__ float g_pv[(size_t)RCAP * 64];
__device__ int   g_pi[(size_t)RCAP * 64];
__device__ float g_enorm[KCODES];
__device__ int   g_idx[M_ROWS];
__device__ int   g_rows[RCAP];
__device__ int   g_nflag;
__device__ float g_part[256];

// ---------------- helpers ----------------
__device__ __forceinline__ void cp16(void* sdst, const void* gsrc){
  unsigned s = (unsigned)__cvta_generic_to_shared(sdst);
  asm volatile("cp.async.cg.shared.global [%0], [%1], 16;\n" :: "r"(s), "l"(gsrc));
}
__device__ __forceinline__ void cp_commit(){ asm volatile("cp.async.commit_group;\n" ::: "memory"); }
__device__ __forceinline__ void cp_wait0(){ asm volatile("cp.async.wait_group 0;\n" ::: "memory"); }
__device__ __forceinline__ void cp_wait1(){ asm volatile("cp.async.wait_group 1;\n" ::: "memory"); }
__device__ __forceinline__ uint32_t smem_u32(const void* p){
  uint32_t a; asm("{ .reg .u64 t; cvta.to.shared.u64 t, %1; cvt.u32.u64 %0, t; }" : "=r"(a) : "l"(p));
  return a;
}
#define LDSM4(r, addr) asm volatile( \
  "ldmatrix.sync.aligned.m8n8.x4.shared.b16 {%0,%1,%2,%3}, [%4];" \
  : "=r"((r)[0]), "=r"((r)[1]), "=r"((r)[2]), "=r"((r)[3]) : "r"(addr))
#define MMA16816(c, a, b) asm volatile( \
  "mma.sync.aligned.m16n8k16.row.col.f32.f16.f16.f32 " \
  "{%0,%1,%2,%3}, {%4,%5,%6,%7}, {%8,%9}, {%0,%1,%2,%3};" \
  : "+f"((c)[0]), "+f"((c)[1]), "+f"((c)[2]), "+f"((c)[3]) \
  : "r"((a)[0]), "r"((a)[1]), "r"((a)[2]), "r"((a)[3]), "r"((b)[0]), "r"((b)[1]))

// packed fp32x2 fma: two independent fp32 lanes, identical rounding to fmaf
#define FFMA2(acc2, a2, b2) \
  asm("fma.rn.f32x2 %0, %1, %2, %0;" : "+l"(acc2) : "l"(a2), "l"(b2))
#define PACK2(dst, lo, hi) \
  asm("mov.b64 %0, {%1, %2};" : "=l"(dst) : "f"(lo), "f"(hi))
#define UNPACK2(lo, hi, src) \
  asm("mov.b64 {%0, %1}, %2;" : "=f"(lo), "=f"(hi) : "l"(src))

union SmemGemm {
  struct { float As[2][16][128]; float Bs[2][16][128]; } g;
  struct { float rv[128][16]; int ri[128][16]; } r;
};

// ---------------- transpose (x only) ----------------
__global__ void transpose_k(const float* __restrict__ src, float* __restrict__ dst, int R, int C){
  __shared__ float t[32][33];
  int bx = blockIdx.x * 32, by = blockIdx.y * 32;
  int x = bx + threadIdx.x;
  #pragma unroll
  for (int i = threadIdx.y; i < 32; i += 8) t[i][threadIdx.x] = src[(size_t)(by + i) * C + x];
  __syncthreads();
  int xo = by + threadIdx.x;
  #pragma unroll
  for (int i = threadIdx.y; i < 32; i += 8) dst[(size_t)(bx + i) * R + xo] = t[threadIdx.x][i];
}

// ----- fused codebook prep: cbT + fp16 + exact enorm + nflag reset ---------
__global__ void cb_prep_k(const float* __restrict__ cb){
  __shared__ float buf[32][257];
  const int tid = threadIdx.x;
  int rbase = blockIdx.x * 32;
  for (int lin = tid; lin < 32 * 256; lin += blockDim.x){
    int r = lin >> 8, c = lin & 255;
    float v = cb[(size_t)(rbase + r) * DDIM + c];
    buf[r][c] = v;
    g_cbf16[(size_t)(rbase + r) * DDIM + c] = __float2half_rn(v);
  }
  __syncthreads();
  if (tid < 32){
    int r = tid;
    float s = 0.f;
    #pragma unroll 8
    for (int i = 0; i < 256; i++){ float v = buf[r][i]; s = __fadd_rn(s, __fmul_rn(v, v)); }
    g_enorm[rbase + r] = s;
  }
  for (int lin = tid; lin < 32 * 256; lin += blockDim.x){
    int d = lin >> 5, k = lin & 31;
    g_cbT[(size_t)d * KCODES + rbase + k] = buf[k][d];
  }
  if (blockIdx.x == 0 && tid == 0) g_nflag = 0;
}

// ---------------- GEMM1 exact (FFMA2 packed) + fp16 emit ----------------
#define G1_LOAD(kc, buf) do {                                                   \
  int k0_ = (kc) * 16;                                                          \
  cp16(&sm.g.As[buf][lk  ][lr], g_xT + (size_t)(k0_+lk  )*M_ROWS + rbase + lr); \
  cp16(&sm.g.As[buf][lk+8][lr], g_xT + (size_t)(k0_+lk+8)*M_ROWS + rbase + lr); \
  cp16(&sm.g.Bs[buf][lk  ][lr], W    + (size_t)(k0_+lk  )*DDIM   + cbase + lr); \
  cp16(&sm.g.Bs[buf][lk+8][lr], W    + (size_t)(k0_+lk+8)*DDIM   + cbase + lr); \
} while(0)

__global__ __launch_bounds__(256, 2) void gemm1_k(const float* __restrict__ W,
                                                  const float* __restrict__ bias){
  __shared__ SmemGemm sm;
  const int tid = threadIdx.x;
  const int tx = tid & 15, ty = tid >> 4;
  const int rbase = blockIdx.y * 128;
  const int cbase = blockIdx.x * 128;
  const int lk = tid >> 5;
  const int lr = (tid & 31) << 2;

  // acc2[i][jp] = packed lanes (acc[i][2jp], acc[i][2jp+1]); each lane is an
  // independent fp32 fma chain over ascending k -> bitwise == scalar fmaf.
  uint64_t acc2[8][4];
  #pragma unroll
  for (int i = 0; i < 8; i++)
    #pragma unroll
    for (int jp = 0; jp < 4; jp++) acc2[i][jp] = 0ull;

  G1_LOAD(0, 0); cp_commit(); cp_wait0(); __syncthreads();
  for (int kc = 0; kc < ZC/16; kc++){
    int cur = kc & 1;
    if (kc + 1 < ZC/16){ G1_LOAD(kc + 1, cur ^ 1); cp_commit(); }
    const float (*Asc)[128] = sm.g.As[cur];
    const float (*Bsc)[128] = sm.g.Bs[cur];
    #pragma unroll
    for (int k = 0; k < 16; k++){
      float4 a0 = *(const float4*)&Asc[k][ty*4];
      float4 a1 = *(const float4*)&Asc[k][64 + ty*4];
      float4 b0 = *(const float4*)&Bsc[k][tx*4];
      float4 b1 = *(const float4*)&Bsc[k][64 + tx*4];
      float a[8] = {a0.x,a0.y,a0.z,a0.w,a1.x,a1.y,a1.z,a1.w};
      uint64_t b2[4];
      PACK2(b2[0], b0.x, b0.y); PACK2(b2[1], b0.z, b0.w);
      PACK2(b2[2], b1.x, b1.y); PACK2(b2[3], b1.z, b1.w);
      #pragma unroll
      for (int i = 0; i < 8; i++){
        uint64_t a2; PACK2(a2, a[i], a[i]);
        #pragma unroll
        for (int jp = 0; jp < 4; jp++)
          FFMA2(acc2[i][jp], a2, b2[jp]);
      }
    }
    cp_wait0(); __syncthreads();
  }
  #pragma unroll
  for (int jg = 0; jg < 2; jg++){
    int c = cbase + (jg ? 64 + tx*4 : tx*4);
    float4 bv = *(const float4*)&bias[c];
    #pragma unroll
    for (int i = 0; i < 8; i++){
      int r = rbase + ((i < 4) ? ty*4 + i : 64 + ty*4 + (i - 4));
      float v0, v1, v2, v3;
      UNPACK2(v0, v1, acc2[i][jg*2+0]);
      UNPACK2(v2, v3, acc2[i][jg*2+1]);
      float4 o;
      o.x = __fadd_rn(v0, bv.x);
      o.y = __fadd_rn(v1, bv.y);
      o.z = __fadd_rn(v2, bv.z);
      o.w = __fadd_rn(v3, bv.w);
      *(float4*)&g_h[(size_t)r * DDIM + c] = o;
      __half2 p01 = __floats2half2_rn(o.x, o.y);
      __half2 p23 = __floats2half2_rn(o.z, o.w);
      uint2 u; u.x = *(uint32_t*)&p01; u.y = *(uint32_t*)&p23;
      *(uint2*)(g_hf16 + (size_t)r * DDIM + c) = u;
    }
  }
}

// -------- approx distance via mma.sync fp16 (512 thr, frag-pipelined) ------
__global__ __launch_bounds__(512, 1) void approx_mma_k(){
  extern __shared__ char dsm[];
  const uint32_t aB = smem_u32(dsm);
  const int tid = threadIdx.x;
  const int lane = tid & 31, w = tid >> 5;
  const int wm = w >> 2, wn = w & 3;
  const int rbase = blockIdx.x * 128;
  const int gid = lane >> 2, tig = lane & 3;
  const uint32_t bbase[2] = { aB + 67584u, aB + 135168u };

  #pragma unroll
  for (int i = 0; i < 8; i++){
    int lin = i * 512 + tid, row = lin >> 5, seg = lin & 31;
    cp16(dsm + row * ROWB + seg * 16, g_hf16 + (size_t)(rbase + row) * 256 + seg * 8);
  }
  #pragma unroll
  for (int i = 0; i < 8; i++){
    int lin = i * 512 + tid, row = lin >> 5, seg = lin & 31;
    cp16(dsm + 67584 + row * ROWB + seg * 16, g_cbf16 + (size_t)row * 256 + seg * 8);
  }
  cp_commit();
  #pragma unroll
  for (int i = 0; i < 8; i++){
    int lin = i * 512 + tid, row = lin >> 5, seg = lin & 31;
    cp16(dsm + 135168 + row * ROWB + seg * 16, g_cbf16 + (size_t)(128 + row) * 256 + seg * 8);
  }
  cp_commit();

  float min1[4], min2[4]; int idx1[4];
  #pragma unroll
  for (int s = 0; s < 4; s++){ min1[s] = 3.4e38f; min2[s] = 3.4e38f; idx1[s] = 0; }

  uint32_t aoff[2];
  #pragma unroll
  for (int mi = 0; mi < 2; mi++)
    aoff[mi] = aB + (uint32_t)(wm*32 + mi*16 + (lane & 15)) * ROWB + ((lane >> 4) * 16);
  uint32_t boff[2];
  {
    int g = lane >> 3;
    #pragma unroll
    for (int ni = 0; ni < 2; ni++)
      boff[ni] = (uint32_t)(wn*32 + ni*16 + ((g >> 1) & 1) * 8 + (lane & 7)) * ROWB
                 + ((g & 1) * 16);
  }

  float acc[2][4][4];
  #pragma unroll
  for (int mi = 0; mi < 2; mi++)
    #pragma unroll
    for (int ni = 0; ni < 4; ni++)
      #pragma unroll
      for (int q = 0; q < 4; q++) acc[mi][ni][q] = 0.f;

  for (int ct = 0; ct < 64; ct++){
    if (ct + 1 < 64) cp_wait1(); else cp_wait0();
    __syncthreads();
    uint32_t bb = bbase[ct & 1];

    uint32_t ar[2][2][4], br[2][2][4];
    LDSM4(ar[0][0], aoff[0]); LDSM4(ar[0][1], aoff[1]);
    LDSM4(br[0][0], bb + boff[0]); LDSM4(br[0][1], bb + boff[1]);
    #pragma unroll
    for (int kk = 0; kk < 16; kk++){
      int p = kk & 1;
      if (kk < 15){
        LDSM4(ar[p^1][0], aoff[0] + (kk+1) * 32);
        LDSM4(ar[p^1][1], aoff[1] + (kk+1) * 32);
        LDSM4(br[p^1][0], bb + boff[0] + (kk+1) * 32);
        LDSM4(br[p^1][1], bb + boff[1] + (kk+1) * 32);
      }
      #pragma unroll
      for (int mi = 0; mi < 2; mi++)
        #pragma unroll
        for (int j = 0; j < 4; j++)
          MMA16816(acc[mi][j], ar[p][mi], &br[p][j >> 1][(j & 1) * 2]);
    }
    __syncthreads();
    if (ct + 2 < 64){
      int c2 = ct + 2;
      char* dst = dsm + (size_t)67584 * (1 + (ct & 1));
      #pragma unroll
      for (int i = 0; i < 8; i++){
        int lin = i * 512 + tid, row = lin >> 5, seg = lin & 31;
        cp16(dst + row * ROWB + seg * 16, g_cbf16 + (size_t)(c2 * 128 + row) * 256 + seg * 8);
      }
      cp_commit();
    }
    int cb0 = ct * 128 + wn * 32;
    #pragma unroll
    for (int mi = 0; mi < 2; mi++)
      #pragma unroll
      for (int h = 0; h < 2; h++){
        int s = mi * 2 + h;
        #pragma unroll
        for (int ni = 0; ni < 4; ni++){
          int c = cb0 + ni * 8 + 2 * tig;
          float2 en = __ldg((const float2*)&g_enorm[c]);
          float sc0 = fmaf(-2.f, acc[mi][ni][h*2+0], en.x);
          float sc1 = fmaf(-2.f, acc[mi][ni][h*2+1], en.y);
          if (sc0 < min1[s]){ min2[s] = min1[s]; min1[s] = sc0; idx1[s] = c; }
          else if (sc0 < min2[s]) min2[s] = sc0;
          if (sc1 < min1[s]){ min2[s] = min1[s]; min1[s] = sc1; idx1[s] = c + 1; }
          else if (sc1 < min2[s]) min2[s] = sc1;
          acc[mi][ni][h*2+0] = 0.f;
          acc[mi][ni][h*2+1] = 0.f;
        }
      }
  }

  __syncthreads();
  float* rv  = (float*)dsm;
  float* rv2 = (float*)(dsm + 8192);
  int*   ri  = (int*)  (dsm + 16384);
  int cg = wn * 4 + tig;
  #pragma unroll
  for (int s = 0; s < 4; s++){
    int row = wm * 32 + (s >> 1) * 16 + (s & 1) * 8 + gid;
    rv [row * 16 + cg] = min1[s];
    rv2[row * 16 + cg] = min2[s];
    ri [row * 16 + cg] = idx1[s];
  }
  __syncthreads();
  if (tid < 128){
    float bv = rv[tid * 16], bv2 = rv2[tid * 16]; int bi = ri[tid * 16];
    #pragma unroll
    for (int g = 1; g < 16; g++){
      float v = rv[tid * 16 + g], v2 = rv2[tid * 16 + g];
      int ix = ri[tid * 16 + g];
      if (v < bv){ bv2 = fminf(bv, v2); bv = v; bi = ix; }
      else { if (v == bv && ix < bi) bi = ix; bv2 = fminf(bv2, v); }
    }
    g_idx[rbase + tid] = bi;
    if (bv2 - bv < DELTA){
      int sl = atomicAdd(&g_nflag, 1);
      if (sl < RCAP) g_rows[sl] = rbase + tid;
    }
  }
}

// ----- rescue gather: k-major copy + exact znorm (same sequential chain) ---
__global__ void gather_rescue_k(){
  int nf = g_nflag; if (nf > RCAP) nf = RCAP;
  for (int f = blockIdx.x * blockDim.x + threadIdx.x; f < nf; f += gridDim.x * blockDim.x){
    int r = g_rows[f];
    const float* src = g_h + (size_t)r * DDIM;
    float s = 0.f;
    for (int k = 0; k < DDIM; k++){
      float v = src[k];
      s = __fadd_rn(s, __fmul_rn(v, v));
      g_hTr[(size_t)k * RCAP + f] = v;
    }
    g_znr[f] = s;
  }
}

// ------- rescue partial: exact 128x128 tile, code-split over blockIdx.x ----
__global__ __launch_bounds__(256, 2) void rescue_part_k(){
  int nf = g_nflag; if (nf > RCAP) nf = RCAP;
  if ((int)blockIdx.y * 128 >= nf) return;
  __shared__ SmemGemm sm;
  const int tid = threadIdx.x;
  const int tx = tid & 15, ty = tid >> 4;
  const int rbase = blockIdx.y * 128;
  const int cbase = blockIdx.x * 128;
  const int lk = tid >> 5;
  const int lr = (tid & 31) << 2;

  float acc[8][8];
  #pragma unroll
  for (int i = 0; i < 8; i++)
    #pragma unroll
    for (int j = 0; j < 8; j++) acc[i][j] = 0.f;

#define RS_LOAD(kc, buf) do {                                                     \
  int k0_ = (kc) * 16;                                                            \
  cp16(&sm.g.As[buf][lk  ][lr], g_hTr + (size_t)(k0_+lk  )*RCAP   + rbase + lr);  \
  cp16(&sm.g.As[buf][lk+8][lr], g_hTr + (size_t)(k0_+lk+8)*RCAP   + rbase + lr);  \
  cp16(&sm.g.Bs[buf][lk  ][lr], g_cbT + (size_t)(k0_+lk  )*KCODES + cbase + lr);  \
  cp16(&sm.g.Bs[buf][lk+8][lr], g_cbT + (size_t)(k0_+lk+8)*KCODES + cbase + lr);  \
} while(0)

  RS_LOAD(0, 0); cp_commit(); cp_wait0(); __syncthreads();
  for (int kc = 0; kc < DDIM/16; kc++){
    int cur = kc & 1;
    if (kc + 1 < DDIM/16){ RS_LOAD(kc + 1, cur ^ 1); cp_commit(); }
    const float (*Asc)[128] = sm.g.As[cur];
    const float (*Bsc)[128] = sm.g.Bs[cur];
    #pragma unroll
    for (int k = 0; k < 16; k++){
      float4 a0 = *(const float4*)&Asc[k][ty*4];
      float4 a1 = *(const float4*)&Asc[k][64 + ty*4];
      float4 b0 = *(const float4*)&Bsc[k][tx*4];
      float4 b1 = *(const float4*)&Bsc[k][64 + tx*4];
      float a[8] = {a0.x,a0.y,a0.z,a0.w,a1.x,a1.y,a1.z,a1.w};
      float bb[8] = {b0.x,b0.y,b0.z,b0.w,b1.x,b1.y,b1.z,b1.w};
      #pragma unroll
      for (int i = 0; i < 8; i++)
        #pragma unroll
        for (int j = 0; j < 8; j++)
          acc[i][j] = fmaf(a[i], bb[j], acc[i][j]);
    }
    cp_wait0(); __syncthreads();
  }
  float minv[8]; int mini[8]; float zn[8];
  #pragma unroll
  for (int i = 0; i < 8; i++){
    minv[i] = 3.4e38f; mini[i] = 0;
    int rl = (i < 4) ? ty*4 + i : 64 + ty*4 + (i - 4);
    zn[i] = g_znr[rbase + rl];
  }
  #pragma unroll
  for (int j = 0; j < 8; j++){
    int cl = (j < 4) ? tx*4 + j : 64 + tx*4 + (j - 4);
    int c = cbase + cl;
    float e = __ldg(&g_enorm[c]);
    #pragma unroll
    for (int i = 0; i < 8; i++){
      float t  = __fadd_rn(zn[i], e);
      float u2 = __fmul_rn(2.0f, acc[i][j]);
      float sc = __fsub_rn(t, u2);
      if (sc < minv[i]){ minv[i] = sc; mini[i] = c; }
    }
  }
  __syncthreads();
  #pragma unroll
  for (int i = 0; i < 8; i++){
    int rl = (i < 4) ? ty*4 + i : 64 + ty*4 + (i - 4);
    sm.r.rv[rl][tx] = minv[i];
    sm.r.ri[rl][tx] = mini[i];
  }
  __syncthreads();
  if (tid < 128){
    float bv = sm.r.rv[tid][0]; int bi = sm.r.ri[tid][0];
    #pragma unroll
    for (int t = 1; t < 16; t++){
      float v = sm.r.rv[tid][t]; int ix = sm.r.ri[tid][t];
      if (v < bv || (v == bv && ix < bi)){ bv = v; bi = ix; }
    }
    g_pv[(size_t)(rbase + tid) * 64 + blockIdx.x] = bv;
    g_pi[(size_t)(rbase + tid) * 64 + blockIdx.x] = bi;
  }
}

__global__ void rescue_final_k(){
  int nf = g_nflag; if (nf > RCAP) nf = RCAP;
  int f = blockIdx.x * blockDim.x + threadIdx.x;
  if (f >= nf) return;
  float bv = g_pv[(size_t)f * 64]; int bi = g_pi[(size_t)f * 64];
  for (int kt = 1; kt < 64; kt++){
    float v = g_pv[(size_t)f * 64 + kt];
    int ix = g_pi[(size_t)f * 64 + kt];
    if (v < bv || (v == bv && ix < bi)){ bv = v; bi = ix; }
  }
  g_idx[g_rows[f]] = bi;
}

// ---------------- gather/loss ----------------
__global__ void gather_loss_k(const float* __restrict__ cb, float* __restrict__ out){
  const int tid = threadIdx.x;
  const int rbase = blockIdx.x * 128;
  float s = 0.f;
  #pragma unroll 4
  for (int p = 0; p < 32; p++){
    int lin = p * 256 + tid;
    int r = rbase + (lin >> 6);
    int c = (lin & 63) << 2;
    int id = __ldg(&g_idx[r]);
    float4 e  = *(const float4*)&cb[(size_t)id * DDIM + c];
    float4 hh = *(const float4*)&g_h[(size_t)r * DDIM + c];
    float dx = e.x - hh.x, dy = e.y - hh.y, dz = e.z - hh.z, dw = e.w - hh.w;
    s += dx*dx + dy*dy + dz*dz + dw*dw;
    *(float4*)&out[(size_t)r * DDIM + c] = e;
  }
  __shared__ float red[256];
  red[tid] = s; __syncthreads();
  #pragma unroll
  for (int o = 128; o > 0; o >>= 1){
    if (tid < o) red[tid] += red[tid + o];
    __syncthreads();
  }
  if (tid == 0) g_part[blockIdx.x] = red[0];
}

__global__ void final_loss_k(float* __restrict__ out, long long pos){
  __shared__ float red[256];
  int tid = threadIdx.x;
  red[tid] = g_part[tid];
  __syncthreads();
  #pragma unroll
  for (int o = 128; o > 0; o >>= 1){
    if (tid < o) red[tid] += red[tid + o];
    __syncthreads();
  }
  if (tid == 0) out[pos] = 1.25f * red[0] / 8388608.0f;
}

// ---------------- launch ----------------
extern "C" void kernel_launch(void* const* d_in, const int* in_sizes, int n_in,
                              void* d_out, int out_size){
  (void)in_sizes; (void)n_in;
  const float* x  = (const float*)d_in[0];
  const float* W  = (const float*)d_in[1];
  const float* b  = (const float*)d_in[2];
  const float* cb = (const float*)d_in[3];
  float* out = (float*)d_out;

  void *pxT = 0;
  cudaGetSymbolAddress(&pxT, g_xT);

  const int DSM = 3 * 67584;   // A + 2 B stages = 198 KB
  cudaFuncSetAttribute(approx_mma_k, cudaFuncAttributeMaxDynamicSharedMemorySize, DSM);

  transpose_k<<<dim3(ZC/32, M_ROWS/32), dim3(32,8)>>>(x, (float*)pxT, M_ROWS, ZC);
  cb_prep_k<<<KCODES/32, 256>>>(cb);
  gemm1_k<<<dim3(DDIM/128, M_ROWS/128), 256>>>(W, b);
  approx_mma_k<<<M_ROWS/128, 512, DSM>>>();
  gather_rescue_k<<<16, 256>>>();
  rescue_part_k<<<dim3(64, RCAP/128), 256>>>();
  rescue_final_k<<<RCAP/128, 128>>>();
  gather_loss_k<<<256, 256>>>(cb, out);
  final_loss_k<<<1, 256>>>(out, (long long)out_size - 1);
}

// round 16
// speedup vs baseline: 1.0561x; 1.0070x over previous
#include <cuda_runtime.h>
#include <cuda_fp16.h>
#include <cstdint>

#define M_ROWS 32768
#define ZC     512
#define DDIM   256
#define KCODES 8192
#define RCAP   8192
#define DELTA  1e-2f
#define ROWB   528          // smem row stride bytes (264 fp16)
#define NSM    148

// ---------------- scratch ----------------
__device__ float g_xT[(size_t)ZC * M_ROWS];
__device__ float g_h[(size_t)M_ROWS * DDIM];
__device__ float g_cbT[(size_t)DDIM * KCODES];
__device__ __half g_hf16[(size_t)M_ROWS * DDIM];
__device__ __half g_cbf16[(size_t)KCODES * DDIM];
__device__ float g_hTr[(size_t)DDIM * RCAP];
__device__ float g_znr[RCAP];
__device__ float g_pv[(size_t)RCAP * 64];
__device__ int   g_pi[(size_t)RCAP * 64];
__device__ float g_enorm[KCODES];
__device__ int   g_idx[M_ROWS];
__device__ int   g_rows[RCAP];
__device__ int   g_nflag;
__device__ float g_part[256];

// ---------------- helpers ----------------
__device__ __forceinline__ void cp16(void* sdst, const void* gsrc){
  unsigned s = (unsigned)__cvta_generic_to_shared(sdst);
  asm volatile("cp.async.cg.shared.global [%0], [%1], 16;\n" :: "r"(s), "l"(gsrc));
}
__device__ __forceinline__ void cp_commit(){ asm volatile("cp.async.commit_group;\n" ::: "memory"); }
__device__ __forceinline__ void cp_wait0(){ asm volatile("cp.async.wait_group 0;\n" ::: "memory"); }
__device__ __forceinline__ void cp_wait1(){ asm volatile("cp.async.wait_group 1;\n" ::: "memory"); }
__device__ __forceinline__ uint32_t smem_u32(const void* p){
  uint32_t a; asm("{ .reg .u64 t; cvta.to.shared.u64 t, %1; cvt.u32.u64 %0, t; }" : "=r"(a) : "l"(p));
  return a;
}
#define LDSM4(r, addr) asm volatile( \
  "ldmatrix.sync.aligned.m8n8.x4.shared.b16 {%0,%1,%2,%3}, [%4];" \
  : "=r"((r)[0]), "=r"((r)[1]), "=r"((r)[2]), "=r"((r)[3]) : "r"(addr))
#define MMA16816(c, a, b) asm volatile( \
  "mma.sync.aligned.m16n8k16.row.col.f32.f16.f16.f32 " \
  "{%0,%1,%2,%3}, {%4,%5,%6,%7}, {%8,%9}, {%0,%1,%2,%3};" \
  : "+f"((c)[0]), "+f"((c)[1]), "+f"((c)[2]), "+f"((c)[3]) \
  : "r"((a)[0]), "r"((a)[1]), "r"((a)[2]), "r"((a)[3]), "r"((b)[0]), "r"((b)[1]))

// packed fp32x2 fma: two independent fp32 lanes, identical rounding to fmaf
#define FFMA2(acc2, a2, b2) \
  asm("fma.rn.f32x2 %0, %1, %2, %0;" : "+l"(acc2) : "l"(a2), "l"(b2))
#define PACK2(dst, lo, hi) \
  asm("mov.b64 %0, {%1, %2};" : "=l"(dst) : "f"(lo), "f"(hi))
#define UNPACK2(lo, hi, src) \
  asm("mov.b64 {%0, %1}, %2;" : "=f"(lo), "=f"(hi) : "l"(src))

union SmemGemm {
  struct { float As[2][16][128]; float Bs[2][16][128]; } g;
  struct { float rv[128][16]; int ri[128][16]; } r;
};

// ---------------- transpose (x only) ----------------
__global__ void transpose_k(const float* __restrict__ src, float* __restrict__ dst, int R, int C){
  __shared__ float t[32][33];
  int bx = blockIdx.x * 32, by = blockIdx.y * 32;
  int x = bx + threadIdx.x;
  #pragma unroll
  for (int i = threadIdx.y; i < 32; i += 8) t[i][threadIdx.x] = src[(size_t)(by + i) * C + x];
  __syncthreads();
  int xo = by + threadIdx.x;
  #pragma unroll
  for (int i = threadIdx.y; i < 32; i += 8) dst[(size_t)(bx + i) * R + xo] = t[threadIdx.x][i];
}

// ----- fused codebook prep: cbT + fp16 + exact enorm + nflag reset ---------
__global__ void cb_prep_k(const float* __restrict__ cb){
  __shared__ float buf[32][257];
  const int tid = threadIdx.x;
  int rbase = blockIdx.x * 32;
  for (int lin = tid; lin < 32 * 256; lin += blockDim.x){
    int r = lin >> 8, c = lin & 255;
    float v = cb[(size_t)(rbase + r) * DDIM + c];
    buf[r][c] = v;
    g_cbf16[(size_t)(rbase + r) * DDIM + c] = __float2half_rn(v);
  }
  __syncthreads();
  if (tid < 32){
    int r = tid;
    float s = 0.f;
    #pragma unroll 8
    for (int i = 0; i < 256; i++){ float v = buf[r][i]; s = __fadd_rn(s, __fmul_rn(v, v)); }
    g_enorm[rbase + r] = s;
  }
  for (int lin = tid; lin < 32 * 256; lin += blockDim.x){
    int d = lin >> 5, k = lin & 31;
    g_cbT[(size_t)d * KCODES + rbase + k] = buf[k][d];
  }
  if (blockIdx.x == 0 && tid == 0) g_nflag = 0;
}

// ---------------- GEMM1 exact (FFMA2 packed) + fp16 emit ----------------
#define G1_LOAD(kc, buf) do {                                                   \
  int k0_ = (kc) * 16;                                                          \
  cp16(&sm.g.As[buf][lk  ][lr], g_xT + (size_t)(k0_+lk  )*M_ROWS + rbase + lr); \
  cp16(&sm.g.As[buf][lk+8][lr], g_xT + (size_t)(k0_+lk+8)*M_ROWS + rbase + lr); \
  cp16(&sm.g.Bs[buf][lk  ][lr], W    + (size_t)(k0_+lk  )*DDIM   + cbase + lr); \
  cp16(&sm.g.Bs[buf][lk+8][lr], W    + (size_t)(k0_+lk+8)*DDIM   + cbase + lr); \
} while(0)

__global__ __launch_bounds__(256, 2) void gemm1_k(const float* __restrict__ W,
                                                  const float* __restrict__ bias){
  __shared__ SmemGemm sm;
  const int tid = threadIdx.x;
  const int tx = tid & 15, ty = tid >> 4;
  const int rbase = blockIdx.y * 128;
  const int cbase = blockIdx.x * 128;
  const int lk = tid >> 5;
  const int lr = (tid & 31) << 2;

  uint64_t acc2[8][4];
  #pragma unroll
  for (int i = 0; i < 8; i++)
    #pragma unroll
    for (int jp = 0; jp < 4; jp++) acc2[i][jp] = 0ull;

  G1_LOAD(0, 0); cp_commit(); cp_wait0(); __syncthreads();
  for (int kc = 0; kc < ZC/16; kc++){
    int cur = kc & 1;
    if (kc + 1 < ZC/16){ G1_LOAD(kc + 1, cur ^ 1); cp_commit(); }
    const float (*Asc)[128] = sm.g.As[cur];
    const float (*Bsc)[128] = sm.g.Bs[cur];
    #pragma unroll
    for (int k = 0; k < 16; k++){
      float4 a0 = *(const float4*)&Asc[k][ty*4];
      float4 a1 = *(const float4*)&Asc[k][64 + ty*4];
      float4 b0 = *(const float4*)&Bsc[k][tx*4];
      float4 b1 = *(const float4*)&Bsc[k][64 + tx*4];
      float a[8] = {a0.x,a0.y,a0.z,a0.w,a1.x,a1.y,a1.z,a1.w};
      uint64_t b2[4];
      PACK2(b2[0], b0.x, b0.y); PACK2(b2[1], b0.z, b0.w);
      PACK2(b2[2], b1.x, b1.y); PACK2(b2[3], b1.z, b1.w);
      #pragma unroll
      for (int i = 0; i < 8; i++){
        uint64_t a2; PACK2(a2, a[i], a[i]);
        #pragma unroll
        for (int jp = 0; jp < 4; jp++)
          FFMA2(acc2[i][jp], a2, b2[jp]);
      }
    }
    cp_wait0(); __syncthreads();
  }
  #pragma unroll
  for (int jg = 0; jg < 2; jg++){
    int c = cbase + (jg ? 64 + tx*4 : tx*4);
    float4 bv = *(const float4*)&bias[c];
    #pragma unroll
    for (int i = 0; i < 8; i++){
      int r = rbase + ((i < 4) ? ty*4 + i : 64 + ty*4 + (i - 4));
      float v0, v1, v2, v3;
      UNPACK2(v0, v1, acc2[i][jg*2+0]);
      UNPACK2(v2, v3, acc2[i][jg*2+1]);
      float4 o;
      o.x = __fadd_rn(v0, bv.x);
      o.y = __fadd_rn(v1, bv.y);
      o.z = __fadd_rn(v2, bv.z);
      o.w = __fadd_rn(v3, bv.w);
      *(float4*)&g_h[(size_t)r * DDIM + c] = o;
      __half2 p01 = __floats2half2_rn(o.x, o.y);
      __half2 p23 = __floats2half2_rn(o.z, o.w);
      uint2 u; u.x = *(uint32_t*)&p01; u.y = *(uint32_t*)&p23;
      *(uint2*)(g_hf16 + (size_t)r * DDIM + c) = u;
    }
  }
}

// -------- approx distance: persistent balanced grid (148 CTAs) -------------
// Each CTA owns a contiguous balanced row range (multiple of 8), processed in
// <=128-row sub-tiles; per sub-tile the full codebook is streamed (64 chunks).
// score = enorm - 2m (zn folded out: per-row shift, argmin/gap invariant)
__global__ __launch_bounds__(512, 1) void approx_mma_k(){
  extern __shared__ char dsm[];
  const uint32_t aB = smem_u32(dsm);
  const int tid = threadIdx.x;
  const int lane = tid & 31, w = tid >> 5;
  const int wm = w >> 2, wn = w & 3;
  const int gid = lane >> 2, tig = lane & 3;
  const uint32_t bbase[2] = { aB + 67584u, aB + 135168u };

  const int r0 = ((blockIdx.x * (M_ROWS / 8)) / NSM) * 8;
  const int r1 = (((blockIdx.x + 1) * (M_ROWS / 8)) / NSM) * 8;

  uint32_t aoff[2];
  #pragma unroll
  for (int mi = 0; mi < 2; mi++)
    aoff[mi] = aB + (uint32_t)(wm*32 + mi*16 + (lane & 15)) * ROWB + ((lane >> 4) * 16);
  uint32_t boff[2];
  {
    int g = lane >> 3;
    #pragma unroll
    for (int ni = 0; ni < 2; ni++)
      boff[ni] = (uint32_t)(wn*32 + ni*16 + ((g >> 1) & 1) * 8 + (lane & 7)) * ROWB
                 + ((g & 1) * 16);
  }

  for (int rb = r0; rb < r1; rb += 128){
    const int sub = min(128, r1 - rb);

    // A sub-tile (rows clamped into this CTA's range) + B chunks 0,1
    #pragma unroll
    for (int i = 0; i < 8; i++){
      int lin = i * 512 + tid, row = lin >> 5, seg = lin & 31;
      int gr = rb + row; if (gr >= r1) gr = r1 - 1;
      cp16(dsm + row * ROWB + seg * 16, g_hf16 + (size_t)gr * 256 + seg * 8);
    }
    #pragma unroll
    for (int i = 0; i < 8; i++){
      int lin = i * 512 + tid, row = lin >> 5, seg = lin & 31;
      cp16(dsm + 67584 + row * ROWB + seg * 16, g_cbf16 + (size_t)row * 256 + seg * 8);
    }
    cp_commit();
    #pragma unroll
    for (int i = 0; i < 8; i++){
      int lin = i * 512 + tid, row = lin >> 5, seg = lin & 31;
      cp16(dsm + 135168 + row * ROWB + seg * 16, g_cbf16 + (size_t)(128 + row) * 256 + seg * 8);
    }
    cp_commit();

    float min1[4], min2[4]; int idx1[4];
    #pragma unroll
    for (int s = 0; s < 4; s++){ min1[s] = 3.4e38f; min2[s] = 3.4e38f; idx1[s] = 0; }

    float acc[2][4][4];
    #pragma unroll
    for (int mi = 0; mi < 2; mi++)
      #pragma unroll
      for (int ni = 0; ni < 4; ni++)
        #pragma unroll
        for (int q = 0; q < 4; q++) acc[mi][ni][q] = 0.f;

    for (int ct = 0; ct < 64; ct++){
      if (ct + 1 < 64) cp_wait1(); else cp_wait0();
      __syncthreads();
      uint32_t bb = bbase[ct & 1];

      uint32_t ar[2][2][4], br[2][2][4];
      LDSM4(ar[0][0], aoff[0]); LDSM4(ar[0][1], aoff[1]);
      LDSM4(br[0][0], bb + boff[0]); LDSM4(br[0][1], bb + boff[1]);
      #pragma unroll
      for (int kk = 0; kk < 16; kk++){
        int p = kk & 1;
        if (kk < 15){
          LDSM4(ar[p^1][0], aoff[0] + (kk+1) * 32);
          LDSM4(ar[p^1][1], aoff[1] + (kk+1) * 32);
          LDSM4(br[p^1][0], bb + boff[0] + (kk+1) * 32);
          LDSM4(br[p^1][1], bb + boff[1] + (kk+1) * 32);
        }
        #pragma unroll
        for (int mi = 0; mi < 2; mi++)
          #pragma unroll
          for (int j = 0; j < 4; j++)
            MMA16816(acc[mi][j], ar[p][mi], &br[p][j >> 1][(j & 1) * 2]);
      }
      __syncthreads();
      if (ct + 2 < 64){
        int c2 = ct + 2;
        char* dst = dsm + (size_t)67584 * (1 + (ct & 1));
        #pragma unroll
        for (int i = 0; i < 8; i++){
          int lin = i * 512 + tid, row = lin >> 5, seg = lin & 31;
          cp16(dst + row * ROWB + seg * 16, g_cbf16 + (size_t)(c2 * 128 + row) * 256 + seg * 8);
        }
        cp_commit();
      }
      int cb0 = ct * 128 + wn * 32;
      #pragma unroll
      for (int mi = 0; mi < 2; mi++)
        #pragma unroll
        for (int h = 0; h < 2; h++){
          int s = mi * 2 + h;
          #pragma unroll
          for (int ni = 0; ni < 4; ni++){
            int c = cb0 + ni * 8 + 2 * tig;
            float2 en = __ldg((const float2*)&g_enorm[c]);
            float sc0 = fmaf(-2.f, acc[mi][ni][h*2+0], en.x);
            float sc1 = fmaf(-2.f, acc[mi][ni][h*2+1], en.y);
            if (sc0 < min1[s]){ min2[s] = min1[s]; min1[s] = sc0; idx1[s] = c; }
            else if (sc0 < min2[s]) min2[s] = sc0;
            if (sc1 < min1[s]){ min2[s] = min1[s]; min1[s] = sc1; idx1[s] = c + 1; }
            else if (sc1 < min2[s]) min2[s] = sc1;
            acc[mi][ni][h*2+0] = 0.f;
            acc[mi][ni][h*2+1] = 0.f;
          }
        }
    }

    // cross-thread top-2 merge (16 col-groups per row), overlay on A region
    __syncthreads();
    float* rv  = (float*)dsm;
    float* rv2 = (float*)(dsm + 8192);
    int*   ri  = (int*)  (dsm + 16384);
    int cg = wn * 4 + tig;
    #pragma unroll
    for (int s = 0; s < 4; s++){
      int row = wm * 32 + (s >> 1) * 16 + (s & 1) * 8 + gid;
      rv [row * 16 + cg] = min1[s];
      rv2[row * 16 + cg] = min2[s];
      ri [row * 16 + cg] = idx1[s];
    }
    __syncthreads();
    if (tid < sub){
      float bv = rv[tid * 16], bv2 = rv2[tid * 16]; int bi = ri[tid * 16];
      #pragma unroll
      for (int g = 1; g < 16; g++){
        float v = rv[tid * 16 + g], v2 = rv2[tid * 16 + g];
        int ix = ri[tid * 16 + g];
        if (v < bv){ bv2 = fminf(bv, v2); bv = v; bi = ix; }
        else { if (v == bv && ix < bi) bi = ix; bv2 = fminf(bv2, v); }
      }
      g_idx[rb + tid] = bi;
      if (bv2 - bv < DELTA){
        int sl = atomicAdd(&g_nflag, 1);
        if (sl < RCAP) g_rows[sl] = rb + tid;
      }
    }
    __syncthreads();   // protect overlay region before next sub-tile's A load
  }
}

// ----- rescue gather: k-major copy + exact znorm (same sequential chain) ---
__global__ void gather_rescue_k(){
  int nf = g_nflag; if (nf > RCAP) nf = RCAP;
  for (int f = blockIdx.x * blockDim.x + threadIdx.x; f < nf; f += gridDim.x * blockDim.x){
    int r = g_rows[f];
    const float* src = g_h + (size_t)r * DDIM;
    float s = 0.f;
    for (int k = 0; k < DDIM; k++){
      float v = src[k];
      s = __fadd_rn(s, __fmul_rn(v, v));
      g_hTr[(size_t)k * RCAP + f] = v;
    }
    g_znr[f] = s;
  }
}

// ------- rescue partial: exact 128x128 tile, code-split over blockIdx.x ----
__global__ __launch_bounds__(256, 2) void rescue_part_k(){
  int nf = g_nflag; if (nf > RCAP) nf = RCAP;
  if ((int)blockIdx.y * 128 >= nf) return;
  __shared__ SmemGemm sm;
  const int tid = threadIdx.x;
  const int tx = tid & 15, ty = tid >> 4;
  const int rbase = blockIdx.y * 128;
  const int cbase = blockIdx.x * 128;
  const int lk = tid >> 5;
  const int lr = (tid & 31) << 2;

  float acc[8][8];
  #pragma unroll
  for (int i = 0; i < 8; i++)
    #pragma unroll
    for (int j = 0; j < 8; j++) acc[i][j] = 0.f;

#define RS_LOAD(kc, buf) do {                                                     \
  int k0_ = (kc) * 16;                                                            \
  cp16(&sm.g.As[buf][lk  ][lr], g_hTr + (size_t)(k0_+lk  )*RCAP   + rbase + lr);  \
  cp16(&sm.g.As[buf][lk+8][lr], g_hTr + (size_t)(k0_+lk+8)*RCAP   + rbase + lr);  \
  cp16(&sm.g.Bs[buf][lk  ][lr], g_cbT + (size_t)(k0_+lk  )*KCODES + cbase + lr);  \
  cp16(&sm.g.Bs[buf][lk+8][lr], g_cbT + (size_t)(k0_+lk+8)*KCODES + cbase + lr);  \
} while(0)

  RS_LOAD(0, 0); cp_commit(); cp_wait0(); __syncthreads();
  for (int kc = 0; kc < DDIM/16; kc++){
    int cur = kc & 1;
    if (kc + 1 < DDIM/16){ RS_LOAD(kc + 1, cur ^ 1); cp_commit(); }
    const float (*Asc)[128] = sm.g.As[cur];
    const float (*Bsc)[128] = sm.g.Bs[cur];
    #pragma unroll
    for (int k = 0; k < 16; k++){
      float4 a0 = *(const float4*)&Asc[k][ty*4];
      float4 a1 = *(const float4*)&Asc[k][64 + ty*4];
      float4 b0 = *(const float4*)&Bsc[k][tx*4];
      float4 b1 = *(const float4*)&Bsc[k][64 + tx*4];
      float a[8] = {a0.x,a0.y,a0.z,a0.w,a1.x,a1.y,a1.z,a1.w};
      float bb[8] = {b0.x,b0.y,b0.z,b0.w,b1.x,b1.y,b1.z,b1.w};
      #pragma unroll
      for (int i = 0; i < 8; i++)
        #pragma unroll
        for (int j = 0; j < 8; j++)
          acc[i][j] = fmaf(a[i], bb[j], acc[i][j]);
    }
    cp_wait0(); __syncthreads();
  }
  float minv[8]; int mini[8]; float zn[8];
  #pragma unroll
  for (int i = 0; i < 8; i++){
    minv[i] = 3.4e38f; mini[i] = 0;
    int rl = (i < 4) ? ty*4 + i : 64 + ty*4 + (i - 4);
    zn[i] = g_znr[rbase + rl];
  }
  #pragma unroll
  for (int j = 0; j < 8; j++){
    int cl = (j < 4) ? tx*4 + j : 64 + tx*4 + (j - 4);
    int c = cbase + cl;
    float e = __ldg(&g_enorm[c]);
    #pragma unroll
    for (int i = 0; i < 8; i++){
      float t  = __fadd_rn(zn[i], e);
      float u2 = __fmul_rn(2.0f, acc[i][j]);
      float sc = __fsub_rn(t, u2);
      if (sc < minv[i]){ minv[i] = sc; mini[i] = c; }
    }
  }
  __syncthreads();
  #pragma unroll
  for (int i = 0; i < 8; i++){
    int rl = (i < 4) ? ty*4 + i : 64 + ty*4 + (i - 4);
    sm.r.rv[rl][tx] = minv[i];
    sm.r.ri[rl][tx] = mini[i];
  }
  __syncthreads();
  if (tid < 128){
    float bv = sm.r.rv[tid][0]; int bi = sm.r.ri[tid][0];
    #pragma unroll
    for (int t = 1; t < 16; t++){
      float v = sm.r.rv[tid][t]; int ix = sm.r.ri[tid][t];
      if (v < bv || (v == bv && ix < bi)){ bv = v; bi = ix; }
    }
    g_pv[(size_t)(rbase + tid) * 64 + blockIdx.x] = bv;
    g_pi[(size_t)(rbase + tid) * 64 + blockIdx.x] = bi;
  }
}

__global__ void rescue_final_k(){
  int nf = g_nflag; if (nf > RCAP) nf = RCAP;
  int f = blockIdx.x * blockDim.x + threadIdx.x;
  if (f >= nf) return;
  float bv = g_pv[(size_t)f * 64]; int bi = g_pi[(size_t)f * 64];
  for (int kt = 1; kt < 64; kt++){
    float v = g_pv[(size_t)f * 64 + kt];
    int ix = g_pi[(size_t)f * 64 + kt];
    if (v < bv || (v == bv && ix < bi)){ bv = v; bi = ix; }
  }
  g_idx[g_rows[f]] = bi;
}

// ---------------- gather/loss ----------------
__global__ void gather_loss_k(const float* __restrict__ cb, float* __restrict__ out){
  const int tid = threadIdx.x;
  const int rbase = blockIdx.x * 128;
  float s = 0.f;
  #pragma unroll 4
  for (int p = 0; p < 32; p++){
    int lin = p * 256 + tid;
    int r = rbase + (lin >> 6);
    int c = (lin & 63) << 2;
    int id = __ldg(&g_idx[r]);
    float4 e  = *(const float4*)&cb[(size_t)id * DDIM + c];
    float4 hh = *(const float4*)&g_h[(size_t)r * DDIM + c];
    float dx = e.x - hh.x, dy = e.y - hh.y, dz = e.z - hh.z, dw = e.w - hh.w;
    s += dx*dx + dy*dy + dz*dz + dw*dw;
    *(float4*)&out[(size_t)r * DDIM + c] = e;
  }
  __shared__ float red[256];
  red[tid] = s; __syncthreads();
  #pragma unroll
  for (int o = 128; o > 0; o >>= 1){
    if (tid < o) red[tid] += red[tid + o];
    __syncthreads();
  }
  if (tid == 0) g_part[blockIdx.x] = red[0];
}

__global__ void final_loss_k(float* __restrict__ out, long long pos){
  __shared__ float red[256];
  int tid = threadIdx.x;
  red[tid] = g_part[tid];
  __syncthreads();
  #pragma unroll
  for (int o = 128; o > 0; o >>= 1){
    if (tid < o) red[tid] += red[tid + o];
    __syncthreads();
  }
  if (tid == 0) out[pos] = 1.25f * red[0] / 8388608.0f;
}

// ---------------- launch ----------------
extern "C" void kernel_launch(void* const* d_in, const int* in_sizes, int n_in,
                              void* d_out, int out_size){
  (void)in_sizes; (void)n_in;
  const float* x  = (const float*)d_in[0];
  const float* W  = (const float*)d_in[1];
  const float* b  = (const float*)d_in[2];
  const float* cb = (const float*)d_in[3];
  float* out = (float*)d_out;

  void *pxT = 0;
  cudaGetSymbolAddress(&pxT, g_xT);

  const int DSM = 3 * 67584;   // A + 2 B stages = 198 KB
  cudaFuncSetAttribute(approx_mma_k, cudaFuncAttributeMaxDynamicSharedMemorySize, DSM);

  transpose_k<<<dim3(ZC/32, M_ROWS/32), dim3(32,8)>>>(x, (float*)pxT, M_ROWS, ZC);
  cb_prep_k<<<KCODES/32, 256>>>(cb);
  gemm1_k<<<dim3(DDIM/128, M_ROWS/128), 256>>>(W, b);
  approx_mma_k<<<NSM, 512, DSM>>>();
  gather_rescue_k<<<16, 256>>>();
  rescue_part_k<<<dim3(64, RCAP/128), 256>>>();
  rescue_final_k<<<RCAP/128, 128>>>();
  gather_loss_k<<<256, 256>>>(cb, out);
  final_loss_k<<<1, 256>>>(out, (long long)out_size - 1);
}

// round 17
// speedup vs baseline: 1.1319x; 1.0718x over previous
#include <cuda_runtime.h>
#include <cuda_fp16.h>
#include <cstdint>

#define M_ROWS 32768
#define ZC     512
#define DDIM   256
#define KCODES 8192
#define RCAP   8192
#define DELTA  1e-2f
#define ROWB   528          // smem row stride bytes (264 fp16)
#define NSM    148
#define NUNITS 2048         // 256 row-tiles x 8 code-eighths

// ---------------- scratch ----------------
__device__ float g_xT[(size_t)ZC * M_ROWS];
__device__ float g_h[(size_t)M_ROWS * DDIM];
__device__ float g_cbT[(size_t)DDIM * KCODES];
__device__ __half g_hf16[(size_t)M_ROWS * DDIM];
__device__ __half g_cbf16[(size_t)KCODES * DDIM];
__device__ float g_hTr[(size_t)DDIM * RCAP];
__device__ float g_znr[RCAP];
__device__ float g_pv[(size_t)RCAP * 64];
__device__ int   g_pi[(size_t)RCAP * 64];
__device__ float g_s1[(size_t)M_ROWS * 8];
__device__ float g_s2[(size_t)M_ROWS * 8];
__device__ int   g_si[(size_t)M_ROWS * 8];
__device__ float g_enorm[KCODES];
__device__ int   g_idx[M_ROWS];
__device__ int   g_rows[RCAP];
__device__ int   g_nflag;
__device__ float g_part[256];

// ---------------- helpers ----------------
__device__ __forceinline__ void cp16(void* sdst, const void* gsrc){
  unsigned s = (unsigned)__cvta_generic_to_shared(sdst);
  asm volatile("cp.async.cg.shared.global [%0], [%1], 16;\n" :: "r"(s), "l"(gsrc));
}
__device__ __forceinline__ void cp_commit(){ asm volatile("cp.async.commit_group;\n" ::: "memory"); }
__device__ __forceinline__ void cp_wait0(){ asm volatile("cp.async.wait_group 0;\n" ::: "memory"); }
__device__ __forceinline__ void cp_wait1(){ asm volatile("cp.async.wait_group 1;\n" ::: "memory"); }
__device__ __forceinline__ uint32_t smem_u32(const void* p){
  uint32_t a; asm("{ .reg .u64 t; cvta.to.shared.u64 t, %1; cvt.u32.u64 %0, t; }" : "=r"(a) : "l"(p));
  return a;
}
#define LDSM4(r, addr) asm volatile( \
  "ldmatrix.sync.aligned.m8n8.x4.shared.b16 {%0,%1,%2,%3}, [%4];" \
  : "=r"((r)[0]), "=r"((r)[1]), "=r"((r)[2]), "=r"((r)[3]) : "r"(addr))
#define MMA16816(c, a, b) asm volatile( \
  "mma.sync.aligned.m16n8k16.row.col.f32.f16.f16.f32 " \
  "{%0,%1,%2,%3}, {%4,%5,%6,%7}, {%8,%9}, {%0,%1,%2,%3};" \
  : "+f"((c)[0]), "+f"((c)[1]), "+f"((c)[2]), "+f"((c)[3]) \
  : "r"((a)[0]), "r"((a)[1]), "r"((a)[2]), "r"((a)[3]), "r"((b)[0]), "r"((b)[1]))

#define FFMA2(acc2, a2, b2) \
  asm("fma.rn.f32x2 %0, %1, %2, %0;" : "+l"(acc2) : "l"(a2), "l"(b2))
#define PACK2(dst, lo, hi) \
  asm("mov.b64 %0, {%1, %2};" : "=l"(dst) : "f"(lo), "f"(hi))
#define UNPACK2(lo, hi, src) \
  asm("mov.b64 {%0, %1}, %2;" : "=f"(lo), "=f"(hi) : "l"(src))

union SmemGemm {
  struct { float As[2][16][128]; float Bs[2][16][128]; } g;
  struct { float rv[128][16]; int ri[128][16]; } r;
};

// ---------------- transpose (x only) ----------------
__global__ void transpose_k(const float* __restrict__ src, float* __restrict__ dst, int R, int C){
  __shared__ float t[32][33];
  int bx = blockIdx.x * 32, by = blockIdx.y * 32;
  int x = bx + threadIdx.x;
  #pragma unroll
  for (int i = threadIdx.y; i < 32; i += 8) t[i][threadIdx.x] = src[(size_t)(by + i) * C + x];
  __syncthreads();
  int xo = by + threadIdx.x;
  #pragma unroll
  for (int i = threadIdx.y; i < 32; i += 8) dst[(size_t)(bx + i) * R + xo] = t[threadIdx.x][i];
}

// -- fused cb prep: cbT + fp16 + exact enorm + nflag reset + slot init ------
__global__ void cb_prep_k(const float* __restrict__ cb){
  __shared__ float buf[32][257];
  const int tid = threadIdx.x;
  int rbase = blockIdx.x * 32;
  for (int lin = tid; lin < 32 * 256; lin += blockDim.x){
    int r = lin >> 8, c = lin & 255;
    float v = cb[(size_t)(rbase + r) * DDIM + c];
    buf[r][c] = v;
    g_cbf16[(size_t)(rbase + r) * DDIM + c] = __float2half_rn(v);
  }
  __syncthreads();
  if (tid < 32){
    int r = tid;
    float s = 0.f;
    #pragma unroll 8
    for (int i = 0; i < 256; i++){ float v = buf[r][i]; s = __fadd_rn(s, __fmul_rn(v, v)); }
    g_enorm[rbase + r] = s;
  }
  for (int lin = tid; lin < 32 * 256; lin += blockDim.x){
    int d = lin >> 5, k = lin & 31;
    g_cbT[(size_t)d * KCODES + rbase + k] = buf[k][d];
  }
  // partial-slot init (grid 256 x 256 covers 262144 in 4 strides)
  for (int i = blockIdx.x * 256 + tid; i < M_ROWS * 8; i += 256 * 256){
    g_s1[i] = 3.4e38f; g_s2[i] = 3.4e38f; g_si[i] = 0x7fffffff;
  }
  if (blockIdx.x == 0 && tid == 0) g_nflag = 0;
}

// ---------------- GEMM1 exact (FFMA2 packed) + fp16 emit ----------------
#define G1_LOAD(kc, buf) do {                                                   \
  int k0_ = (kc) * 16;                                                          \
  cp16(&sm.g.As[buf][lk  ][lr], g_xT + (size_t)(k0_+lk  )*M_ROWS + rbase + lr); \
  cp16(&sm.g.As[buf][lk+8][lr], g_xT + (size_t)(k0_+lk+8)*M_ROWS + rbase + lr); \
  cp16(&sm.g.Bs[buf][lk  ][lr], W    + (size_t)(k0_+lk  )*DDIM   + cbase + lr); \
  cp16(&sm.g.Bs[buf][lk+8][lr], W    + (size_t)(k0_+lk+8)*DDIM   + cbase + lr); \
} while(0)

__global__ __launch_bounds__(256, 2) void gemm1_k(const float* __restrict__ W,
                                                  const float* __restrict__ bias){
  __shared__ SmemGemm sm;
  const int tid = threadIdx.x;
  const int tx = tid & 15, ty = tid >> 4;
  const int rbase = blockIdx.y * 128;
  const int cbase = blockIdx.x * 128;
  const int lk = tid >> 5;
  const int lr = (tid & 31) << 2;

  uint64_t acc2[8][4];
  #pragma unroll
  for (int i = 0; i < 8; i++)
    #pragma unroll
    for (int jp = 0; jp < 4; jp++) acc2[i][jp] = 0ull;

  G1_LOAD(0, 0); cp_commit(); cp_wait0(); __syncthreads();
  for (int kc = 0; kc < ZC/16; kc++){
    int cur = kc & 1;
    if (kc + 1 < ZC/16){ G1_LOAD(kc + 1, cur ^ 1); cp_commit(); }
    const float (*Asc)[128] = sm.g.As[cur];
    const float (*Bsc)[128] = sm.g.Bs[cur];
    #pragma unroll
    for (int k = 0; k < 16; k++){
      float4 a0 = *(const float4*)&Asc[k][ty*4];
      float4 a1 = *(const float4*)&Asc[k][64 + ty*4];
      float4 b0 = *(const float4*)&Bsc[k][tx*4];
      float4 b1 = *(const float4*)&Bsc[k][64 + tx*4];
      float a[8] = {a0.x,a0.y,a0.z,a0.w,a1.x,a1.y,a1.z,a1.w};
      uint64_t b2[4];
      PACK2(b2[0], b0.x, b0.y); PACK2(b2[1], b0.z, b0.w);
      PACK2(b2[2], b1.x, b1.y); PACK2(b2[3], b1.z, b1.w);
      #pragma unroll
      for (int i = 0; i < 8; i++){
        uint64_t a2; PACK2(a2, a[i], a[i]);
        #pragma unroll
        for (int jp = 0; jp < 4; jp++)
          FFMA2(acc2[i][jp], a2, b2[jp]);
      }
    }
    cp_wait0(); __syncthreads();
  }
  #pragma unroll
  for (int jg = 0; jg < 2; jg++){
    int c = cbase + (jg ? 64 + tx*4 : tx*4);
    float4 bv = *(const float4*)&bias[c];
    #pragma unroll
    for (int i = 0; i < 8; i++){
      int r = rbase + ((i < 4) ? ty*4 + i : 64 + ty*4 + (i - 4));
      float v0, v1, v2, v3;
      UNPACK2(v0, v1, acc2[i][jg*2+0]);
      UNPACK2(v2, v3, acc2[i][jg*2+1]);
      float4 o;
      o.x = __fadd_rn(v0, bv.x);
      o.y = __fadd_rn(v1, bv.y);
      o.z = __fadd_rn(v2, bv.z);
      o.w = __fadd_rn(v3, bv.w);
      *(float4*)&g_h[(size_t)r * DDIM + c] = o;
      __half2 p01 = __floats2half2_rn(o.x, o.y);
      __half2 p23 = __floats2half2_rn(o.z, o.w);
      uint2 u; u.x = *(uint32_t*)&p01; u.y = *(uint32_t*)&p23;
      *(uint2*)(g_hf16 + (size_t)r * DDIM + c) = u;
    }
  }
}

// -------- approx distance: persistent 2-D units (128 rows x 1024 codes) ----
// Unit u = t*8 + e (t = row tile, e = code eighth). CTA b owns units
// [b*2048/148, (b+1)*2048/148) -> <=3 contiguous-chunk segments.
// Per segment: stream chunks, per-row partial top-2 -> slot [row][e0].
__global__ __launch_bounds__(512, 1) void approx_mma_k(){
  extern __shared__ char dsm[];
  const uint32_t aB = smem_u32(dsm);
  const int tid = threadIdx.x;
  const int lane = tid & 31, w = tid >> 5;
  const int wm = w >> 2, wn = w & 3;
  const int gid = lane >> 2, tig = lane & 3;
  const uint32_t bbase[2] = { aB + 67584u, aB + 135168u };

  const int u0 = (int)(((unsigned)blockIdx.x * NUNITS) / NSM);
  const int u1 = (int)(((unsigned)(blockIdx.x + 1) * NUNITS) / NSM);

  uint32_t aoff[2];
  #pragma unroll
  for (int mi = 0; mi < 2; mi++)
    aoff[mi] = aB + (uint32_t)(wm*32 + mi*16 + (lane & 15)) * ROWB + ((lane >> 4) * 16);
  uint32_t boff[2];
  {
    int g = lane >> 3;
    #pragma unroll
    for (int ni = 0; ni < 2; ni++)
      boff[ni] = (uint32_t)(wn*32 + ni*16 + ((g >> 1) & 1) * 8 + (lane & 7)) * ROWB
                 + ((g & 1) * 16);
  }

  int u = u0;
  while (u < u1){
    const int t = u >> 3, e0 = u & 7;
    const int e_end = min(8, e0 + (u1 - u));
    const int c0 = e0 * 8, c1 = e_end * 8;    // [c0,c1) chunks of 128 codes
    const int rb = t * 128;

    // A tile + first two B chunks
    #pragma unroll
    for (int i = 0; i < 8; i++){
      int lin = i * 512 + tid, row = lin >> 5, seg = lin & 31;
      cp16(dsm + row * ROWB + seg * 16, g_hf16 + (size_t)(rb + row) * 256 + seg * 8);
    }
    #pragma unroll
    for (int i = 0; i < 8; i++){
      int lin = i * 512 + tid, row = lin >> 5, seg = lin & 31;
      cp16(dsm + 67584 + row * ROWB + seg * 16,
           g_cbf16 + (size_t)(c0 * 128 + row) * 256 + seg * 8);
    }
    cp_commit();
    #pragma unroll
    for (int i = 0; i < 8; i++){
      int lin = i * 512 + tid, row = lin >> 5, seg = lin & 31;
      cp16(dsm + 135168 + row * ROWB + seg * 16,
           g_cbf16 + (size_t)((c0 + 1) * 128 + row) * 256 + seg * 8);
    }
    cp_commit();

    float min1[4], min2[4]; int idx1[4];
    #pragma unroll
    for (int s = 0; s < 4; s++){ min1[s] = 3.4e38f; min2[s] = 3.4e38f; idx1[s] = 0; }

    float acc[2][4][4];
    #pragma unroll
    for (int mi = 0; mi < 2; mi++)
      #pragma unroll
      for (int ni = 0; ni < 4; ni++)
        #pragma unroll
        for (int q = 0; q < 4; q++) acc[mi][ni][q] = 0.f;

    for (int ci = c0; ci < c1; ci++){
      if (ci + 1 < c1) cp_wait1(); else cp_wait0();
      __syncthreads();
      uint32_t bb = bbase[(ci - c0) & 1];

      uint32_t ar[2][2][4], br[2][2][4];
      LDSM4(ar[0][0], aoff[0]); LDSM4(ar[0][1], aoff[1]);
      LDSM4(br[0][0], bb + boff[0]); LDSM4(br[0][1], bb + boff[1]);
      #pragma unroll
      for (int kk = 0; kk < 16; kk++){
        int p = kk & 1;
        if (kk < 15){
          LDSM4(ar[p^1][0], aoff[0] + (kk+1) * 32);
          LDSM4(ar[p^1][1], aoff[1] + (kk+1) * 32);
          LDSM4(br[p^1][0], bb + boff[0] + (kk+1) * 32);
          LDSM4(br[p^1][1], bb + boff[1] + (kk+1) * 32);
        }
        #pragma unroll
        for (int mi = 0; mi < 2; mi++)
          #pragma unroll
          for (int j = 0; j < 4; j++)
            MMA16816(acc[mi][j], ar[p][mi], &br[p][j >> 1][(j & 1) * 2]);
      }
      __syncthreads();
      if (ci + 2 < c1){
        char* dst = dsm + (size_t)67584 * (1 + ((ci - c0) & 1));
        #pragma unroll
        for (int i = 0; i < 8; i++){
          int lin = i * 512 + tid, row = lin >> 5, seg = lin & 31;
          cp16(dst + row * ROWB + seg * 16,
               g_cbf16 + (size_t)((ci + 2) * 128 + row) * 256 + seg * 8);
        }
        cp_commit();
      }
      int cb0 = ci * 128 + wn * 32;
      #pragma unroll
      for (int mi = 0; mi < 2; mi++)
        #pragma unroll
        for (int h = 0; h < 2; h++){
          int s = mi * 2 + h;
          #pragma unroll
          for (int ni = 0; ni < 4; ni++){
            int c = cb0 + ni * 8 + 2 * tig;
            float2 en = __ldg((const float2*)&g_enorm[c]);
            float sc0 = fmaf(-2.f, acc[mi][ni][h*2+0], en.x);
            float sc1 = fmaf(-2.f, acc[mi][ni][h*2+1], en.y);
            if (sc0 < min1[s]){ min2[s] = min1[s]; min1[s] = sc0; idx1[s] = c; }
            else if (sc0 < min2[s]) min2[s] = sc0;
            if (sc1 < min1[s]){ min2[s] = min1[s]; min1[s] = sc1; idx1[s] = c + 1; }
            else if (sc1 < min2[s]) min2[s] = sc1;
            acc[mi][ni][h*2+0] = 0.f;
            acc[mi][ni][h*2+1] = 0.f;
          }
        }
    }

    // cross-thread top-2 merge (16 col-groups per row), overlay on A region
    __syncthreads();
    float* rv  = (float*)dsm;
    float* rv2 = (float*)(dsm + 8192);
    int*   ri  = (int*)  (dsm + 16384);
    int cg = wn * 4 + tig;
    #pragma unroll
    for (int s = 0; s < 4; s++){
      int row = wm * 32 + (s >> 1) * 16 + (s & 1) * 8 + gid;
      rv [row * 16 + cg] = min1[s];
      rv2[row * 16 + cg] = min2[s];
      ri [row * 16 + cg] = idx1[s];
    }
    __syncthreads();
    if (tid < 128){
      float bv = rv[tid * 16], bv2 = rv2[tid * 16]; int bi = ri[tid * 16];
      #pragma unroll
      for (int g = 1; g < 16; g++){
        float v = rv[tid * 16 + g], v2 = rv2[tid * 16 + g];
        int ix = ri[tid * 16 + g];
        if (v < bv){ bv2 = fminf(bv, v2); bv = v; bi = ix; }
        else { if (v == bv && ix < bi) bi = ix; bv2 = fminf(bv2, v); }
      }
      size_t slot = (size_t)(rb + tid) * 8 + e0;
      g_s1[slot] = bv; g_s2[slot] = bv2; g_si[slot] = bi;
    }
    __syncthreads();   // protect overlay before next segment's A load
    u += (e_end - e0);
  }
}

// ----- merge partial top-2 slots -> final idx + flag -----------------------
__global__ void merge_flag_k(){
  int r = blockIdx.x * 256 + threadIdx.x;
  float bv = 3.4e38f, bv2 = 3.4e38f; int bi = 0x7fffffff;
  #pragma unroll
  for (int s = 0; s < 8; s++){
    float v = g_s1[(size_t)r * 8 + s];
    float v2 = g_s2[(size_t)r * 8 + s];
    int ix = g_si[(size_t)r * 8 + s];
    if (v < bv){ bv2 = fminf(bv, v2); bv = v; bi = ix; }
    else { if (v == bv && ix < bi) bi = ix; bv2 = fminf(bv2, v); }
  }
  g_idx[r] = bi;
  if (bv2 - bv < DELTA){
    int sl = atomicAdd(&g_nflag, 1);
    if (sl < RCAP) g_rows[sl] = r;
  }
}

// ----- rescue gather: k-major copy + exact znorm (same sequential chain) ---
__global__ void gather_rescue_k(){
  int nf = g_nflag; if (nf > RCAP) nf = RCAP;
  for (int f = blockIdx.x * blockDim.x + threadIdx.x; f < nf; f += gridDim.x * blockDim.x){
    int r = g_rows[f];
    const float* src = g_h + (size_t)r * DDIM;
    float s = 0.f;
    for (int k = 0; k < DDIM; k++){
      float v = src[k];
      s = __fadd_rn(s, __fmul_rn(v, v));
      g_hTr[(size_t)k * RCAP + f] = v;
    }
    g_znr[f] = s;
  }
}

// ------- rescue partial: exact 128x128 tile, code-split over blockIdx.x ----
__global__ __launch_bounds__(256, 2) void rescue_part_k(){
  int nf = g_nflag; if (nf > RCAP) nf = RCAP;
  if ((int)blockIdx.y * 128 >= nf) return;
  __shared__ SmemGemm sm;
  const int tid = threadIdx.x;
  const int tx = tid & 15, ty = tid >> 4;
  const int rbase = blockIdx.y * 128;
  const int cbase = blockIdx.x * 128;
  const int lk = tid >> 5;
  const int lr = (tid & 31) << 2;

  float acc[8][8];
  #pragma unroll
  for (int i = 0; i < 8; i++)
    #pragma unroll
    for (int j = 0; j < 8; j++) acc[i][j] = 0.f;

#define RS_LOAD(kc, buf) do {                                                     \
  int k0_ = (kc) * 16;                                                            \
  cp16(&sm.g.As[buf][lk  ][lr], g_hTr + (size_t)(k0_+lk  )*RCAP   + rbase + lr);  \
  cp16(&sm.g.As[buf][lk+8][lr], g_hTr + (size_t)(k0_+lk+8)*RCAP   + rbase + lr);  \
  cp16(&sm.g.Bs[buf][lk  ][lr], g_cbT + (size_t)(k0_+lk  )*KCODES + cbase + lr);  \
  cp16(&sm.g.Bs[buf][lk+8][lr], g_cbT + (size_t)(k0_+lk+8)*KCODES + cbase + lr);  \
} while(0)

  RS_LOAD(0, 0); cp_commit(); cp_wait0(); __syncthreads();
  for (int kc = 0; kc < DDIM/16; kc++){
    int cur = kc & 1;
    if (kc + 1 < DDIM/16){ RS_LOAD(kc + 1, cur ^ 1); cp_commit(); }
    const float (*Asc)[128] = sm.g.As[cur];
    const float (*Bsc)[128] = sm.g.Bs[cur];
    #pragma unroll
    for (int k = 0; k < 16; k++){
      float4 a0 = *(const float4*)&Asc[k][ty*4];
      float4 a1 = *(const float4*)&Asc[k][64 + ty*4];
      float4 b0 = *(const float4*)&Bsc[k][tx*4];
      float4 b1 = *(const float4*)&Bsc[k][64 + tx*4];
      float a[8] = {a0.x,a0.y,a0.z,a0.w,a1.x,a1.y,a1.z,a1.w};
      float bb[8] = {b0.x,b0.y,b0.z,b0.w,b1.x,b1.y,b1.z,b1.w};
      #pragma unroll
      for (int i = 0; i < 8; i++)
        #pragma unroll
        for (int j = 0; j < 8; j++)
          acc[i][j] = fmaf(a[i], bb[j], acc[i][j]);
    }
    cp_wait0(); __syncthreads();
  }
  float minv[8]; int mini[8]; float zn[8];
  #pragma unroll
  for (int i = 0; i < 8; i++){
    minv[i] = 3.4e38f; mini[i] = 0;
    int rl = (i < 4) ? ty*4 + i : 64 + ty*4 + (i - 4);
    zn[i] = g_znr[rbase + rl];
  }
  #pragma unroll
  for (int j = 0; j < 8; j++){
    int cl = (j < 4) ? tx*4 + j : 64 + tx*4 + (j - 4);
    int c = cbase + cl;
    float e = __ldg(&g_enorm[c]);
    #pragma unroll
    for (int i = 0; i < 8; i++){
      float t  = __fadd_rn(zn[i], e);
      float u2 = __fmul_rn(2.0f, acc[i][j]);
      float sc = __fsub_rn(t, u2);
      if (sc < minv[i]){ minv[i] = sc; mini[i] = c; }
    }
  }
  __syncthreads();
  #pragma unroll
  for (int i = 0; i < 8; i++){
    int rl = (i < 4) ? ty*4 + i : 64 + ty*4 + (i - 4);
    sm.r.rv[rl][tx] = minv[i];
    sm.r.ri[rl][tx] = mini[i];
  }
  __syncthreads();
  if (tid < 128){
    float bv = sm.r.rv[tid][0]; int bi = sm.r.ri[tid][0];
    #pragma unroll
    for (int t = 1; t < 16; t++){
      float v = sm.r.rv[tid][t]; int ix = sm.r.ri[tid][t];
      if (v < bv || (v == bv && ix < bi)){ bv = v; bi = ix; }
    }
    g_pv[(size_t)(rbase + tid) * 64 + blockIdx.x] = bv;
    g_pi[(size_t)(rbase + tid) * 64 + blockIdx.x] = bi;
  }
}

__global__ void rescue_final_k(){
  int nf = g_nflag; if (nf > RCAP) nf = RCAP;
  int f = blockIdx.x * blockDim.x + threadIdx.x;
  if (f >= nf) return;
  float bv = g_pv[(size_t)f * 64]; int bi = g_pi[(size_t)f * 64];
  for (int kt = 1; kt < 64; kt++){
    float v = g_pv[(size_t)f * 64 + kt];
    int ix = g_pi[(size_t)f * 64 + kt];
    if (v < bv || (v == bv && ix < bi)){ bv = v; bi = ix; }
  }
  g_idx[g_rows[f]] = bi;
}

// ---------------- gather/loss ----------------
__global__ void gather_loss_k(const float* __restrict__ cb, float* __restrict__ out){
  const int tid = threadIdx.x;
  const int rbase = blockIdx.x * 128;
  float s = 0.f;
  #pragma unroll 4
  for (int p = 0; p < 32; p++){
    int lin = p * 256 + tid;
    int r = rbase + (lin >> 6);
    int c = (lin & 63) << 2;
    int id = __ldg(&g_idx[r]);
    float4 e  = *(const float4*)&cb[(size_t)id * DDIM + c];
    float4 hh = *(const float4*)&g_h[(size_t)r * DDIM + c];
    float dx = e.x - hh.x, dy = e.y - hh.y, dz = e.z - hh.z, dw = e.w - hh.w;
    s += dx*dx + dy*dy + dz*dz + dw*dw;
    *(float4*)&out[(size_t)r * DDIM + c] = e;
  }
  __shared__ float red[256];
  red[tid] = s; __syncthreads();
  #pragma unroll
  for (int o = 128; o > 0; o >>= 1){
    if (tid < o) red[tid] += red[tid + o];
    __syncthreads();
  }
  if (tid == 0) g_part[blockIdx.x] = red[0];
}

__global__ void final_loss_k(float* __restrict__ out, long long pos){
  __shared__ float red[256];
  int tid = threadIdx.x;
  red[tid] = g_part[tid];
  __syncthreads();
  #pragma unroll
  for (int o = 128; o > 0; o >>= 1){
    if (tid < o) red[tid] += red[tid + o];
    __syncthreads();
  }
  if (tid == 0) out[pos] = 1.25f * red[0] / 8388608.0f;
}

// ---------------- launch ----------------
extern "C" void kernel_launch(void* const* d_in, const int* in_sizes, int n_in,
                              void* d_out, int out_size){
  (void)in_sizes; (void)n_in;
  const float* x  = (const float*)d_in[0];
  const float* W  = (const float*)d_in[1];
  const float* b  = (const float*)d_in[2];
  const float* cb = (const float*)d_in[3];
  float* out = (float*)d_out;

  void *pxT = 0;
  cudaGetSymbolAddress(&pxT, g_xT);

  const int DSM = 3 * 67584;   // A + 2 B stages = 198 KB
  cudaFuncSetAttribute(approx_mma_k, cudaFuncAttributeMaxDynamicSharedMemorySize, DSM);

  transpose_k<<<dim3(ZC/32, M_ROWS/32), dim3(32,8)>>>(x, (float*)pxT, M_ROWS, ZC);
  cb_prep_k<<<KCODES/32, 256>>>(cb);
  gemm1_k<<<dim3(DDIM/128, M_ROWS/128), 256>>>(W, b);
  approx_mma_k<<<NSM, 512, DSM>>>();
  merge_flag_k<<<M_ROWS/256, 256>>>();
  gather_rescue_k<<<16, 256>>>();
  rescue_part_k<<<dim3(64, RCAP/128), 256>>>();
  rescue_final_k<<<RCAP/128, 128>>>();
  gather_loss_k<<<256, 256>>>(cb, out);
  final_loss_k<<<1, 256>>>(out, (long long)out_size - 1);
}